// round 8
// baseline (speedup 1.0000x reference)
#include <cuda_runtime.h>
#include <cuda_bf16.h>
#include <stdint.h>
#include <math.h>

// Problem constants
#define BS   4096
#define NE   128
#define NQ   32
#define IND  256
#define EMB  512
#define NH   4
#define HD   128

// -------- scratch (static device globals; no runtime allocation) --------
__device__ float g_k [BS * NE * EMB];
__device__ float g_v [BS * NE * EMB];
__device__ float g_q [BS * NQ * EMB];
__device__ uint8_t g_pre [BS * NQ * NE];
__device__ uint8_t g_post[BS * NQ];
__device__ int     g_mask_kind;
// bf16 hi/lo pre-split operands
__device__ __nv_bfloat16 g_eh [BS * NE * IND], g_el [BS * NE * IND];
__device__ __nv_bfloat16 g_wih[3 * EMB * IND], g_wil[3 * EMB * IND];
__device__ __nv_bfloat16 g_woh[EMB * EMB],     g_wol[EMB * EMB];
__device__ __nv_bfloat16 g_aoh[BS * NQ * EMB], g_aol[BS * NQ * EMB];

// ============================================================================
// Mask dtype sniffer + normalizer (proven)
// ============================================================================
__global__ void sniff_kernel(const void* __restrict__ pre)
{
    __shared__ int s_hasF, s_hasHi;
    if (threadIdx.x == 0) { s_hasF = 0; s_hasHi = 0; }
    __syncthreads();
    const unsigned* w = (const unsigned*)pre;
    int hasF = 0, hasHi = 0;
    for (int i = threadIdx.x; i < 16384; i += blockDim.x) {
        const unsigned v = w[i];
        if (v == 0x3F800000u) hasF = 1;
        if (v & 0xFFFFFF00u)  hasHi = 1;
    }
    if (hasF)  atomicOr(&s_hasF, 1);
    if (hasHi) atomicOr(&s_hasHi, 1);
    __syncthreads();
    if (threadIdx.x == 0)
        g_mask_kind = s_hasF ? 2 : (s_hasHi ? 0 : 1);
}

__global__ void cvt_mask_kernel(const void* __restrict__ src,
                                uint8_t* __restrict__ dst, int n)
{
    const int i = blockIdx.x * blockDim.x + threadIdx.x;
    if (i >= n) return;
    const int k = g_mask_kind;
    uint8_t v;
    if (k == 0)      v = (((const uint8_t*)src)[i] != 0);
    else if (k == 1) v = (((const int*)src)[i] != 0);
    else             v = (((const float*)src)[i] != 0.f);
    dst[i] = v;
}

// ============================================================================
// fp32 -> (bf16 hi, bf16 lo) split, vectorized (4 floats/thread)
// ============================================================================
__global__ void split_kernel(const float* __restrict__ src,
                             __nv_bfloat16* __restrict__ h,
                             __nv_bfloat16* __restrict__ l, int n4)
{
    const int i = blockIdx.x * blockDim.x + threadIdx.x;
    if (i >= n4) return;
    const float4 v = reinterpret_cast<const float4*>(src)[i];
    __nv_bfloat162 h0 = __floats2bfloat162_rn(v.x, v.y);
    __nv_bfloat162 h1 = __floats2bfloat162_rn(v.z, v.w);
    __nv_bfloat162 l0 = __floats2bfloat162_rn(v.x - __bfloat162float(h0.x),
                                              v.y - __bfloat162float(h0.y));
    __nv_bfloat162 l1 = __floats2bfloat162_rn(v.z - __bfloat162float(h1.x),
                                              v.w - __bfloat162float(h1.y));
    uint32_t* hp = reinterpret_cast<uint32_t*>(h);
    uint32_t* lp = reinterpret_cast<uint32_t*>(l);
    hp[2 * i]     = *reinterpret_cast<uint32_t*>(&h0);
    hp[2 * i + 1] = *reinterpret_cast<uint32_t*>(&h1);
    lp[2 * i]     = *reinterpret_cast<uint32_t*>(&l0);
    lp[2 * i + 1] = *reinterpret_cast<uint32_t*>(&l1);
}

// ============================================================================
// bf16 3x-split GEMM with cp.async 3-stage pipeline.
//   C[M,N] = A[M,K] @ W[N,K]^T ~= Ah*Bh + Ah*Bl + Al*Bh  (fp32 accum)
// Tile 128x128, BK=32, 256 thr = 8 warps (2M x 4N), warp = 64x32.
// Stage = {Ah, Al, Bh, Bl} 128x32 bf16 each (8KB), XOR-swizzled rows:
//   quad q at row r lives at r*64 + ((q ^ ((r>>1)&3))<<4)  -> conflict-free
// MODE 0: KV (N=1024 -> g_k/g_v)  MODE 1: Q (row gather)  MODE 2: out-proj
// ============================================================================
#define STAGE_B 32768
#define GEMM_SMEM (3 * STAGE_B)

__device__ __forceinline__ void mma_bf16(float* d, const uint32_t* a,
                                         const uint32_t* b)
{
    asm volatile(
        "mma.sync.aligned.m16n8k16.row.col.f32.bf16.bf16.f32 "
        "{%0,%1,%2,%3}, {%4,%5,%6,%7}, {%8,%9}, {%0,%1,%2,%3};"
        : "+f"(d[0]), "+f"(d[1]), "+f"(d[2]), "+f"(d[3])
        : "r"(a[0]), "r"(a[1]), "r"(a[2]), "r"(a[3]), "r"(b[0]), "r"(b[1]));
}

__device__ __forceinline__ uint32_t smem_u32(const void* p) {
    uint32_t a;
    asm("{ .reg .u64 t; cvta.to.shared.u64 t, %1; cvt.u32.u64 %0, t; }"
        : "=r"(a) : "l"(p));
    return a;
}

// swizzled word load: pair index p (0..15) within row r
__device__ __forceinline__ uint32_t lds32(const char* base, int r, int p) {
    const int q = p >> 2, m = p & 3;
    return *reinterpret_cast<const uint32_t*>(
        base + r * 64 + ((q ^ ((r >> 1) & 3)) << 4) + m * 4);
}

template<int KDIM, int MODE>
__global__ __launch_bounds__(256)
void mma_gemm_bf(const __nv_bfloat16* __restrict__ Ah_g,
                 const __nv_bfloat16* __restrict__ Al_g,
                 const __nv_bfloat16* __restrict__ Bh_g,
                 const __nv_bfloat16* __restrict__ Bl_g,
                 float* __restrict__ Cout,
                 const float* __restrict__ bias)
{
    constexpr int S = KDIM / 32;
    extern __shared__ char smem[];
    const uint32_t sb = smem_u32(smem);

    const int t    = threadIdx.x;
    const int lane = t & 31;
    const int wid  = t >> 5;
    const int wm   = wid >> 2;
    const int wn   = wid & 3;
    const int ntile = blockIdx.x;
    const int mtile = blockIdx.y;
    const int rq = lane >> 2;
    const int pq = lane & 3;

    // issue one stage's cp.async copies (2048 x 16B quads, 8 per thread)
    auto issue = [&](int s, int buf) {
        #pragma unroll
        for (int i = 0; i < 8; i++) {
            const int idx = t + i * 256;
            const int arr = idx >> 9;          // 0=Ah 1=Al 2=Bh 3=Bl
            const int rem = idx & 511;
            const int r   = rem >> 2;
            const int q   = rem & 3;
            const __nv_bfloat16* g;
            if (arr < 2) {
                const int gm = mtile * 128 + r;
                const int arow = (MODE == 1) ? ((gm >> 5) * NE + (gm & 31)) : gm;
                g = (arr == 0 ? Ah_g : Al_g) + (size_t)arow * KDIM + s * 32 + q * 8;
            } else {
                g = (arr == 2 ? Bh_g : Bl_g)
                    + (size_t)(ntile * 128 + r) * KDIM + s * 32 + q * 8;
            }
            const uint32_t dst = sb + buf * STAGE_B + arr * 8192
                               + r * 64 + ((q ^ ((r >> 1) & 3)) << 4);
            asm volatile("cp.async.ca.shared.global [%0], [%1], 16;"
                         :: "r"(dst), "l"(g));
        }
        asm volatile("cp.async.commit_group;" ::: "memory");
    };

    float acc[4][4][4];
    #pragma unroll
    for (int i = 0; i < 4; i++)
        #pragma unroll
        for (int j = 0; j < 4; j++)
            #pragma unroll
            for (int c = 0; c < 4; c++) acc[i][j][c] = 0.f;

    issue(0, 0);
    issue(1, 1);

    for (int s = 0; s < S; s++) {
        asm volatile("cp.async.wait_group 1;" ::: "memory");
        __syncthreads();
        if (s + 2 < S) issue(s + 2, (s + 2) % 3);
        else asm volatile("cp.async.commit_group;" ::: "memory");

        const char* Ahs = smem + (s % 3) * STAGE_B;
        const char* Als = Ahs + 8192;
        const char* Bhs = Ahs + 16384;
        const char* Bls = Ahs + 24576;

        #pragma unroll
        for (int kh = 0; kh < 2; kh++) {
            const int p = kh * 8 + pq;
            uint32_t bh[4][2], bl[4][2];
            #pragma unroll
            for (int nf = 0; nf < 4; nf++) {
                const int row = wn * 32 + nf * 8 + rq;
                bh[nf][0] = lds32(Bhs, row, p);
                bh[nf][1] = lds32(Bhs, row, p + 4);
                bl[nf][0] = lds32(Bls, row, p);
                bl[nf][1] = lds32(Bls, row, p + 4);
            }
            #pragma unroll
            for (int mf = 0; mf < 4; mf++) {
                const int r0 = wm * 64 + mf * 16 + rq;
                const int r8 = r0 + 8;
                uint32_t ah[4], al[4];
                ah[0] = lds32(Ahs, r0, p);     ah[1] = lds32(Ahs, r8, p);
                ah[2] = lds32(Ahs, r0, p + 4); ah[3] = lds32(Ahs, r8, p + 4);
                al[0] = lds32(Als, r0, p);     al[1] = lds32(Als, r8, p);
                al[2] = lds32(Als, r0, p + 4); al[3] = lds32(Als, r8, p + 4);
                #pragma unroll
                for (int nf = 0; nf < 4; nf++) {
                    mma_bf16(acc[mf][nf], ah, bh[nf]);
                    mma_bf16(acc[mf][nf], ah, bl[nf]);
                    mma_bf16(acc[mf][nf], al, bh[nf]);
                }
            }
        }
    }
    asm volatile("cp.async.wait_group 0;" ::: "memory");

    // ---- epilogue: write fp32 results ----
    #pragma unroll
    for (int mf = 0; mf < 4; mf++) {
        #pragma unroll
        for (int nf = 0; nf < 4; nf++) {
            const int r0 = mtile * 128 + wm * 64 + mf * 16 + rq;
            const int r1 = r0 + 8;
            const int gn = ntile * 128 + wn * 32 + nf * 8 + pq * 2;
            float2 v0 = make_float2(acc[mf][nf][0], acc[mf][nf][1]);
            float2 v1 = make_float2(acc[mf][nf][2], acc[mf][nf][3]);
            if (MODE == 0) {
                if (gn < EMB) {
                    *reinterpret_cast<float2*>(&g_k[(size_t)r0 * EMB + gn]) = v0;
                    *reinterpret_cast<float2*>(&g_k[(size_t)r1 * EMB + gn]) = v1;
                } else {
                    *reinterpret_cast<float2*>(&g_v[(size_t)r0 * EMB + gn - EMB]) = v0;
                    *reinterpret_cast<float2*>(&g_v[(size_t)r1 * EMB + gn - EMB]) = v1;
                }
            } else if (MODE == 1) {
                *reinterpret_cast<float2*>(&g_q[(size_t)r0 * EMB + gn]) = v0;
                *reinterpret_cast<float2*>(&g_q[(size_t)r1 * EMB + gn]) = v1;
            } else {
                const float2 bb = *reinterpret_cast<const float2*>(&bias[gn]);
                v0.x += bb.x; v0.y += bb.y;
                v1.x += bb.x; v1.y += bb.y;
                if (g_post[r0]) { v0.x = 0.f; v0.y = 0.f; }
                if (g_post[r1]) { v1.x = 0.f; v1.y = 0.f; }
                *reinterpret_cast<float2*>(&Cout[(size_t)r0 * EMB + gn]) = v0;
                *reinterpret_cast<float2*>(&Cout[(size_t)r1 * EMB + gn]) = v1;
            }
        }
    }
}

// ============================================================================
// Attention: one CTA per (batch, head), fp32 scalar; writes bf16 hi/lo out.
// ============================================================================
#define SST 129
#define ATTN_SMEM ((32 + 128 + 32) * SST * 4)

__global__ __launch_bounds__(256)
void attn_kernel()
{
    const int b = blockIdx.x;
    const int h = blockIdx.y;
    extern __shared__ float sm[];
    float* qs = sm;
    float* kv = sm + 32 * SST;
    float* ls = sm + (32 + 128) * SST;

    const int t  = threadIdx.x;
    const int tx = t & 31;
    const int ty = t >> 5;

    #pragma unroll
    for (int l = 0; l < 4; l++) {
        const int idx = t + l * 256;
        const int qi  = idx >> 5;
        const int dq  = (idx & 31) * 4;
        const float4 v = *reinterpret_cast<const float4*>(
            &g_q[(size_t)(b * NQ + qi) * EMB + h * HD + dq]);
        qs[qi * SST + dq + 0] = v.x; qs[qi * SST + dq + 1] = v.y;
        qs[qi * SST + dq + 2] = v.z; qs[qi * SST + dq + 3] = v.w;
    }
    #pragma unroll
    for (int l = 0; l < 16; l++) {
        const int idx = t + l * 256;
        const int kj  = idx >> 5;
        const int dq  = (idx & 31) * 4;
        const float4 v = *reinterpret_cast<const float4*>(
            &g_k[(size_t)(b * NE + kj) * EMB + h * HD + dq]);
        kv[kj * SST + dq + 0] = v.x; kv[kj * SST + dq + 1] = v.y;
        kv[kj * SST + dq + 2] = v.z; kv[kj * SST + dq + 3] = v.w;
    }
    __syncthreads();

    float acc[4][4];
    #pragma unroll
    for (int i = 0; i < 4; i++)
        #pragma unroll
        for (int j = 0; j < 4; j++) acc[i][j] = 0.f;

    for (int d = 0; d < HD; d++) {
        float a[4], bb[4];
        #pragma unroll
        for (int i = 0; i < 4; i++) a[i]  = qs[(ty + 8 * i) * SST + d];
        #pragma unroll
        for (int j = 0; j < 4; j++) bb[j] = kv[(tx + 32 * j) * SST + d];
        #pragma unroll
        for (int i = 0; i < 4; i++)
            #pragma unroll
            for (int j = 0; j < 4; j++)
                acc[i][j] = fmaf(a[i], bb[j], acc[i][j]);
    }

    const float inv_scale = 0.08838834764831845f;
    const uint8_t* pm = g_pre + (size_t)b * NQ * NE;
    #pragma unroll
    for (int i = 0; i < 4; i++) {
        const int qi = ty + 8 * i;
        #pragma unroll
        for (int j = 0; j < 4; j++) {
            const int kj = tx + 32 * j;
            ls[qi * SST + kj] = pm[qi * NE + kj] ? -1e30f : acc[i][j] * inv_scale;
        }
    }
    __syncthreads();

    #pragma unroll
    for (int l = 0; l < 16; l++) {
        const int idx = t + l * 256;
        const int kj  = idx >> 5;
        const int dq  = (idx & 31) * 4;
        const float4 v = *reinterpret_cast<const float4*>(
            &g_v[(size_t)(b * NE + kj) * EMB + h * HD + dq]);
        kv[kj * SST + dq + 0] = v.x; kv[kj * SST + dq + 1] = v.y;
        kv[kj * SST + dq + 2] = v.z; kv[kj * SST + dq + 3] = v.w;
    }

    {
        const int w    = t >> 5;
        const int lane = t & 31;
        #pragma unroll
        for (int rr = 0; rr < 4; rr++) {
            const int r = w * 4 + rr;
            float x0 = ls[r * SST + lane];
            float x1 = ls[r * SST + lane + 32];
            float x2 = ls[r * SST + lane + 64];
            float x3 = ls[r * SST + lane + 96];
            float mx = fmaxf(fmaxf(x0, x1), fmaxf(x2, x3));
            #pragma unroll
            for (int off = 16; off; off >>= 1)
                mx = fmaxf(mx, __shfl_xor_sync(0xffffffffu, mx, off));
            float e0 = (x0 <= -1e29f) ? 0.f : expf(x0 - mx);
            float e1 = (x1 <= -1e29f) ? 0.f : expf(x1 - mx);
            float e2 = (x2 <= -1e29f) ? 0.f : expf(x2 - mx);
            float e3 = (x3 <= -1e29f) ? 0.f : expf(x3 - mx);
            float s = e0 + e1 + e2 + e3;
            #pragma unroll
            for (int off = 16; off; off >>= 1)
                s += __shfl_xor_sync(0xffffffffu, s, off);
            const float inv = (s > 0.f) ? (1.f / s) : 0.f;
            ls[r * SST + lane]      = e0 * inv;
            ls[r * SST + lane + 32] = e1 * inv;
            ls[r * SST + lane + 64] = e2 * inv;
            ls[r * SST + lane + 96] = e3 * inv;
        }
    }
    __syncthreads();

    float o[4][4];
    #pragma unroll
    for (int i = 0; i < 4; i++)
        #pragma unroll
        for (int j = 0; j < 4; j++) o[i][j] = 0.f;

    for (int kj = 0; kj < NE; kj++) {
        float a[4], bb[4];
        #pragma unroll
        for (int i = 0; i < 4; i++) a[i]  = ls[(ty + 8 * i) * SST + kj];
        #pragma unroll
        for (int j = 0; j < 4; j++) bb[j] = kv[kj * SST + tx + 32 * j];
        #pragma unroll
        for (int i = 0; i < 4; i++)
            #pragma unroll
            for (int j = 0; j < 4; j++)
                o[i][j] = fmaf(a[i], bb[j], o[i][j]);
    }

    // write bf16 hi/lo split directly (consumed by out-proj GEMM)
    #pragma unroll
    for (int i = 0; i < 4; i++) {
        const int qi = ty + 8 * i;
        #pragma unroll
        for (int j = 0; j < 4; j++) {
            const int d = tx + 32 * j;
            const size_t idx = (size_t)(b * NQ + qi) * EMB + h * HD + d;
            const float ov = o[i][j];
            const __nv_bfloat16 hb = __float2bfloat16(ov);
            g_aoh[idx] = hb;
            g_aol[idx] = __float2bfloat16(ov - __bfloat162float(hb));
        }
    }
}

// ============================================================================
extern "C" void kernel_launch(void* const* d_in, const int* in_sizes, int n_in,
                              void* d_out, int out_size)
{
    const float *entities = nullptr, *W_in = nullptr, *W_out = nullptr,
                *b_out = nullptr;
    const void  *pre_mask = nullptr, *post_mask = nullptr;
    for (int i = 0; i < n_in; i++) {
        switch (in_sizes[i]) {
            case BS * NE * IND:   entities  = (const float*)d_in[i]; break;
            case BS * NQ * NE:    pre_mask  = d_in[i];               break;
            case BS * NQ:         post_mask = d_in[i];               break;
            case 3 * EMB * IND:   W_in      = (const float*)d_in[i]; break;
            case EMB * EMB:       W_out     = (const float*)d_in[i]; break;
            case EMB:             b_out     = (const float*)d_in[i]; break;
        }
    }
    float* out = (float*)d_out;

    cudaFuncSetAttribute(attn_kernel,
                         cudaFuncAttributeMaxDynamicSharedMemorySize, ATTN_SMEM);
    cudaFuncSetAttribute(mma_gemm_bf<IND, 0>,
                         cudaFuncAttributeMaxDynamicSharedMemorySize, GEMM_SMEM);
    cudaFuncSetAttribute(mma_gemm_bf<IND, 1>,
                         cudaFuncAttributeMaxDynamicSharedMemorySize, GEMM_SMEM);
    cudaFuncSetAttribute(mma_gemm_bf<EMB, 2>,
                         cudaFuncAttributeMaxDynamicSharedMemorySize, GEMM_SMEM);

    __nv_bfloat16 *eh, *el, *wih, *wil, *woh, *wol, *aoh, *aol;
    uint8_t *pre_dst, *post_dst;
    cudaGetSymbolAddress((void**)&eh,  g_eh);
    cudaGetSymbolAddress((void**)&el,  g_el);
    cudaGetSymbolAddress((void**)&wih, g_wih);
    cudaGetSymbolAddress((void**)&wil, g_wil);
    cudaGetSymbolAddress((void**)&woh, g_woh);
    cudaGetSymbolAddress((void**)&wol, g_wol);
    cudaGetSymbolAddress((void**)&aoh, g_aoh);
    cudaGetSymbolAddress((void**)&aol, g_aol);
    cudaGetSymbolAddress((void**)&pre_dst,  g_pre);
    cudaGetSymbolAddress((void**)&post_dst, g_post);

    // 0) normalize masks + pre-split operands to bf16 hi/lo
    sniff_kernel<<<1, 256>>>(pre_mask);
    cvt_mask_kernel<<<(BS * NQ * NE + 255) / 256, 256>>>(pre_mask, pre_dst,
                                                         BS * NQ * NE);
    cvt_mask_kernel<<<(BS * NQ + 255) / 256, 256>>>(post_mask, post_dst,
                                                    BS * NQ);
    split_kernel<<<(BS * NE * IND / 4 + 255) / 256, 256>>>(entities, eh, el,
                                                           BS * NE * IND / 4);
    split_kernel<<<(3 * EMB * IND / 4 + 255) / 256, 256>>>(W_in, wih, wil,
                                                           3 * EMB * IND / 4);
    split_kernel<<<(EMB * EMB / 4 + 255) / 256, 256>>>(W_out, woh, wol,
                                                       EMB * EMB / 4);

    // 1) K,V projection -> g_k, g_v
    mma_gemm_bf<IND, 0><<<dim3(8, BS), 256, GEMM_SMEM>>>(
        eh, el, wih + (size_t)EMB * IND, wil + (size_t)EMB * IND,
        nullptr, nullptr);

    // 2) Q projection -> g_q
    mma_gemm_bf<IND, 1><<<dim3(4, (BS * NQ) / 128), 256, GEMM_SMEM>>>(
        eh, el, wih, wil, nullptr, nullptr);

    // 3) masked multi-head attention -> g_aoh/g_aol (bf16 split)
    attn_kernel<<<dim3(BS, NH), 256, ATTN_SMEM>>>();

    // 4) output projection + bias + post_mask -> d_out
    mma_gemm_bf<EMB, 2><<<dim3(4, (BS * NQ) / 128), 256, GEMM_SMEM>>>(
        aoh, aol, woh, wol, out, b_out);
}

// round 9
// speedup vs baseline: 1.1144x; 1.1144x over previous
#include <cuda_runtime.h>
#include <cuda_bf16.h>
#include <stdint.h>
#include <math.h>

// Problem constants
#define BS   4096
#define NE   128
#define NQ   32
#define IND  256
#define EMB  512
#define NH   4
#define HD   128

// -------- scratch (static device globals; no runtime allocation) --------
__device__ float g_k [BS * NE * EMB];
__device__ float g_v [BS * NE * EMB];
__device__ float g_q [BS * NQ * EMB];
__device__ uint8_t g_pre [BS * NQ * NE];
__device__ uint8_t g_post[BS * NQ];
__device__ int     g_mask_kind;
// bf16 hi/lo pre-split operands
__device__ __nv_bfloat16 g_eh [BS * NE * IND], g_el [BS * NE * IND];
__device__ __nv_bfloat16 g_wih[3 * EMB * IND], g_wil[3 * EMB * IND];
__device__ __nv_bfloat16 g_woh[EMB * EMB],     g_wol[EMB * EMB];
__device__ __nv_bfloat16 g_aoh[BS * NQ * EMB], g_aol[BS * NQ * EMB];

// ============================================================================
// Mask dtype sniffer + normalizer (proven)
// ============================================================================
__global__ void sniff_kernel(const void* __restrict__ pre)
{
    __shared__ int s_hasF, s_hasHi;
    if (threadIdx.x == 0) { s_hasF = 0; s_hasHi = 0; }
    __syncthreads();
    const unsigned* w = (const unsigned*)pre;
    int hasF = 0, hasHi = 0;
    for (int i = threadIdx.x; i < 16384; i += blockDim.x) {
        const unsigned v = w[i];
        if (v == 0x3F800000u) hasF = 1;
        if (v & 0xFFFFFF00u)  hasHi = 1;
    }
    if (hasF)  atomicOr(&s_hasF, 1);
    if (hasHi) atomicOr(&s_hasHi, 1);
    __syncthreads();
    if (threadIdx.x == 0)
        g_mask_kind = s_hasF ? 2 : (s_hasHi ? 0 : 1);
}

__global__ void cvt_mask_kernel(const void* __restrict__ src,
                                uint8_t* __restrict__ dst, int n)
{
    const int i = blockIdx.x * blockDim.x + threadIdx.x;
    if (i >= n) return;
    const int k = g_mask_kind;
    uint8_t v;
    if (k == 0)      v = (((const uint8_t*)src)[i] != 0);
    else if (k == 1) v = (((const int*)src)[i] != 0);
    else             v = (((const float*)src)[i] != 0.f);
    dst[i] = v;
}

// ============================================================================
// fp32 -> (bf16 hi, bf16 lo) split, vectorized
// ============================================================================
__global__ void split_kernel(const float* __restrict__ src,
                             __nv_bfloat16* __restrict__ h,
                             __nv_bfloat16* __restrict__ l, int n4)
{
    const int i = blockIdx.x * blockDim.x + threadIdx.x;
    if (i >= n4) return;
    const float4 v = reinterpret_cast<const float4*>(src)[i];
    __nv_bfloat162 h0 = __floats2bfloat162_rn(v.x, v.y);
    __nv_bfloat162 h1 = __floats2bfloat162_rn(v.z, v.w);
    __nv_bfloat162 l0 = __floats2bfloat162_rn(v.x - __bfloat162float(h0.x),
                                              v.y - __bfloat162float(h0.y));
    __nv_bfloat162 l1 = __floats2bfloat162_rn(v.z - __bfloat162float(h1.x),
                                              v.w - __bfloat162float(h1.y));
    uint32_t* hp = reinterpret_cast<uint32_t*>(h);
    uint32_t* lp = reinterpret_cast<uint32_t*>(l);
    hp[2 * i]     = *reinterpret_cast<uint32_t*>(&h0);
    hp[2 * i + 1] = *reinterpret_cast<uint32_t*>(&h1);
    lp[2 * i]     = *reinterpret_cast<uint32_t*>(&l0);
    lp[2 * i + 1] = *reinterpret_cast<uint32_t*>(&l1);
}

// ============================================================================
// bf16 3x-split GEMM: cp.async 3-stage pipeline + ldmatrix fragment loads.
//   C[M,N] = A[M,K] @ W[N,K]^T ~= Ah*Bh + Ah*Bl + Al*Bh  (fp32 accum)
// Tile 128x128, BK=32, 256 thr = 8 warps (2M x 4N), warp = 64x32.
// Stage = {Ah, Al, Bh, Bl} 128x32 bf16 (8KB each); row r, 16B quad q at
//   r*64 + ((q ^ ((r>>1)&3))<<4)   (conflict-free for cp.async & ldmatrix)
// ============================================================================
#define STAGE_B 32768
#define GEMM_SMEM (3 * STAGE_B)

__device__ __forceinline__ void mma_bf16(float* d, const uint32_t* a,
                                         const uint32_t* b)
{
    asm volatile(
        "mma.sync.aligned.m16n8k16.row.col.f32.bf16.bf16.f32 "
        "{%0,%1,%2,%3}, {%4,%5,%6,%7}, {%8,%9}, {%0,%1,%2,%3};"
        : "+f"(d[0]), "+f"(d[1]), "+f"(d[2]), "+f"(d[3])
        : "r"(a[0]), "r"(a[1]), "r"(a[2]), "r"(a[3]), "r"(b[0]), "r"(b[1]));
}

__device__ __forceinline__ void ldm_x4(uint32_t* r, uint32_t addr)
{
    asm volatile("ldmatrix.sync.aligned.m8n8.x4.shared.b16 {%0,%1,%2,%3}, [%4];"
                 : "=r"(r[0]), "=r"(r[1]), "=r"(r[2]), "=r"(r[3]) : "r"(addr));
}

__device__ __forceinline__ uint32_t smem_u32(const void* p) {
    uint32_t a;
    asm("{ .reg .u64 t; cvta.to.shared.u64 t, %1; cvt.u32.u64 %0, t; }"
        : "=r"(a) : "l"(p));
    return a;
}

// swizzled byte offset of (row, quad)
__device__ __forceinline__ uint32_t swz(int r, int q) {
    return (uint32_t)(r * 64 + ((q ^ ((r >> 1) & 3)) << 4));
}

template<int KDIM, int MODE>
__global__ __launch_bounds__(256, 2)
void mma_gemm_bf(const __nv_bfloat16* __restrict__ Ah_g,
                 const __nv_bfloat16* __restrict__ Al_g,
                 const __nv_bfloat16* __restrict__ Bh_g,
                 const __nv_bfloat16* __restrict__ Bl_g,
                 float* __restrict__ Cout,
                 const float* __restrict__ bias)
{
    constexpr int S = KDIM / 32;
    extern __shared__ char smem[];
    const uint32_t sb = smem_u32(smem);

    const int t    = threadIdx.x;
    const int lane = t & 31;
    const int wid  = t >> 5;
    const int wm   = wid >> 2;
    const int wn   = wid & 3;
    const int ntile = blockIdx.x;
    const int mtile = blockIdx.y;
    const int rq = lane >> 2;
    const int pq = lane & 3;

    // ldmatrix lane-group geometry
    const int g  = lane >> 3;      // 0..3
    const int lr = lane & 7;       // row within 8x8 block
    // A frag (m16k16): row = wm*64 + mf*16 + ((g&1)?8:0) + lr ; quad = 2kh+(g>>1)
    const int arow_l = wm * 64 + ((g & 1) ? 8 : 0) + lr;
    const int aq_l   = g >> 1;
    // B frag pair (2 x n8k16): row = wn*32 + nfp*16 + ((g>=2)?8:0)+lr ; quad=2kh+(g&1)
    const int brow_l = wn * 32 + ((g >= 2) ? 8 : 0) + lr;
    const int bq_l   = g & 1;

    auto issue = [&](int s, int buf) {
        #pragma unroll
        for (int i = 0; i < 8; i++) {
            const int idx = t + i * 256;
            const int arr = idx >> 9;          // 0=Ah 1=Al 2=Bh 3=Bl
            const int rem = idx & 511;
            const int r   = rem >> 2;
            const int q   = rem & 3;
            const __nv_bfloat16* gp;
            if (arr < 2) {
                const int gm = mtile * 128 + r;
                const int arow = (MODE == 1) ? ((gm >> 5) * NE + (gm & 31)) : gm;
                gp = (arr == 0 ? Ah_g : Al_g) + (size_t)arow * KDIM + s * 32 + q * 8;
            } else {
                gp = (arr == 2 ? Bh_g : Bl_g)
                    + (size_t)(ntile * 128 + r) * KDIM + s * 32 + q * 8;
            }
            const uint32_t dst = sb + buf * STAGE_B + arr * 8192 + swz(r, q);
            asm volatile("cp.async.ca.shared.global [%0], [%1], 16;"
                         :: "r"(dst), "l"(gp));
        }
        asm volatile("cp.async.commit_group;" ::: "memory");
    };

    float acc[4][4][4];
    #pragma unroll
    for (int i = 0; i < 4; i++)
        #pragma unroll
        for (int j = 0; j < 4; j++)
            #pragma unroll
            for (int c = 0; c < 4; c++) acc[i][j][c] = 0.f;

    issue(0, 0);
    issue(1, 1);

    for (int s = 0; s < S; s++) {
        asm volatile("cp.async.wait_group 1;" ::: "memory");
        __syncthreads();
        if (s + 2 < S) issue(s + 2, (s + 2) % 3);
        else asm volatile("cp.async.commit_group;" ::: "memory");

        const uint32_t st = sb + (s % 3) * STAGE_B;   // Ah | Al(+8K) | Bh(+16K) | Bl(+24K)

        #pragma unroll
        for (int kh = 0; kh < 2; kh++) {
            // ---- B fragments: 2 x ldmatrix.x4 per (hi, lo) ----
            uint32_t bh[4][2], bl[4][2];
            #pragma unroll
            for (int nfp = 0; nfp < 2; nfp++) {
                const uint32_t off = swz(brow_l + nfp * 16, 2 * kh + bq_l);
                uint32_t rh[4], rl[4];
                ldm_x4(rh, st + 16384 + off);
                ldm_x4(rl, st + 24576 + off);
                bh[2 * nfp][0] = rh[0]; bh[2 * nfp][1] = rh[1];
                bh[2 * nfp + 1][0] = rh[2]; bh[2 * nfp + 1][1] = rh[3];
                bl[2 * nfp][0] = rl[0]; bl[2 * nfp][1] = rl[1];
                bl[2 * nfp + 1][0] = rl[2]; bl[2 * nfp + 1][1] = rl[3];
            }
            // ---- A fragments + MMAs ----
            #pragma unroll
            for (int mf = 0; mf < 4; mf++) {
                const uint32_t off = swz(arow_l + mf * 16, 2 * kh + aq_l);
                uint32_t ah[4], al[4];
                ldm_x4(ah, st + off);
                ldm_x4(al, st + 8192 + off);
                #pragma unroll
                for (int nf = 0; nf < 4; nf++) {
                    mma_bf16(acc[mf][nf], ah, bh[nf]);
                    mma_bf16(acc[mf][nf], ah, bl[nf]);
                    mma_bf16(acc[mf][nf], al, bh[nf]);
                }
            }
        }
    }
    asm volatile("cp.async.wait_group 0;" ::: "memory");

    // ---- epilogue ----
    #pragma unroll
    for (int mf = 0; mf < 4; mf++) {
        #pragma unroll
        for (int nf = 0; nf < 4; nf++) {
            const int r0 = mtile * 128 + wm * 64 + mf * 16 + rq;
            const int r1 = r0 + 8;
            const int gn = ntile * 128 + wn * 32 + nf * 8 + pq * 2;
            float2 v0 = make_float2(acc[mf][nf][0], acc[mf][nf][1]);
            float2 v1 = make_float2(acc[mf][nf][2], acc[mf][nf][3]);
            if (MODE == 0) {
                if (gn < EMB) {
                    *reinterpret_cast<float2*>(&g_k[(size_t)r0 * EMB + gn]) = v0;
                    *reinterpret_cast<float2*>(&g_k[(size_t)r1 * EMB + gn]) = v1;
                } else {
                    *reinterpret_cast<float2*>(&g_v[(size_t)r0 * EMB + gn - EMB]) = v0;
                    *reinterpret_cast<float2*>(&g_v[(size_t)r1 * EMB + gn - EMB]) = v1;
                }
            } else if (MODE == 1) {
                *reinterpret_cast<float2*>(&g_q[(size_t)r0 * EMB + gn]) = v0;
                *reinterpret_cast<float2*>(&g_q[(size_t)r1 * EMB + gn]) = v1;
            } else {
                const float2 bb = *reinterpret_cast<const float2*>(&bias[gn]);
                v0.x += bb.x; v0.y += bb.y;
                v1.x += bb.x; v1.y += bb.y;
                if (g_post[r0]) { v0.x = 0.f; v0.y = 0.f; }
                if (g_post[r1]) { v1.x = 0.f; v1.y = 0.f; }
                *reinterpret_cast<float2*>(&Cout[(size_t)r0 * EMB + gn]) = v0;
                *reinterpret_cast<float2*>(&Cout[(size_t)r1 * EMB + gn]) = v1;
            }
        }
    }
}

// ============================================================================
// Attention: one CTA per (batch, head), fp32 scalar; writes bf16 hi/lo out.
// ============================================================================
#define SST 129
#define ATTN_SMEM ((32 + 128 + 32) * SST * 4)

__global__ __launch_bounds__(256)
void attn_kernel()
{
    const int b = blockIdx.x;
    const int h = blockIdx.y;
    extern __shared__ float sm[];
    float* qs = sm;
    float* kv = sm + 32 * SST;
    float* ls = sm + (32 + 128) * SST;

    const int t  = threadIdx.x;
    const int tx = t & 31;
    const int ty = t >> 5;

    #pragma unroll
    for (int l = 0; l < 4; l++) {
        const int idx = t + l * 256;
        const int qi  = idx >> 5;
        const int dq  = (idx & 31) * 4;
        const float4 v = *reinterpret_cast<const float4*>(
            &g_q[(size_t)(b * NQ + qi) * EMB + h * HD + dq]);
        qs[qi * SST + dq + 0] = v.x; qs[qi * SST + dq + 1] = v.y;
        qs[qi * SST + dq + 2] = v.z; qs[qi * SST + dq + 3] = v.w;
    }
    #pragma unroll
    for (int l = 0; l < 16; l++) {
        const int idx = t + l * 256;
        const int kj  = idx >> 5;
        const int dq  = (idx & 31) * 4;
        const float4 v = *reinterpret_cast<const float4*>(
            &g_k[(size_t)(b * NE + kj) * EMB + h * HD + dq]);
        kv[kj * SST + dq + 0] = v.x; kv[kj * SST + dq + 1] = v.y;
        kv[kj * SST + dq + 2] = v.z; kv[kj * SST + dq + 3] = v.w;
    }
    __syncthreads();

    float acc[4][4];
    #pragma unroll
    for (int i = 0; i < 4; i++)
        #pragma unroll
        for (int j = 0; j < 4; j++) acc[i][j] = 0.f;

    for (int d = 0; d < HD; d++) {
        float a[4], bb[4];
        #pragma unroll
        for (int i = 0; i < 4; i++) a[i]  = qs[(ty + 8 * i) * SST + d];
        #pragma unroll
        for (int j = 0; j < 4; j++) bb[j] = kv[(tx + 32 * j) * SST + d];
        #pragma unroll
        for (int i = 0; i < 4; i++)
            #pragma unroll
            for (int j = 0; j < 4; j++)
                acc[i][j] = fmaf(a[i], bb[j], acc[i][j]);
    }

    const float inv_scale = 0.08838834764831845f;
    const uint8_t* pm = g_pre + (size_t)b * NQ * NE;
    #pragma unroll
    for (int i = 0; i < 4; i++) {
        const int qi = ty + 8 * i;
        #pragma unroll
        for (int j = 0; j < 4; j++) {
            const int kj = tx + 32 * j;
            ls[qi * SST + kj] = pm[qi * NE + kj] ? -1e30f : acc[i][j] * inv_scale;
        }
    }
    __syncthreads();

    #pragma unroll
    for (int l = 0; l < 16; l++) {
        const int idx = t + l * 256;
        const int kj  = idx >> 5;
        const int dq  = (idx & 31) * 4;
        const float4 v = *reinterpret_cast<const float4*>(
            &g_v[(size_t)(b * NE + kj) * EMB + h * HD + dq]);
        kv[kj * SST + dq + 0] = v.x; kv[kj * SST + dq + 1] = v.y;
        kv[kj * SST + dq + 2] = v.z; kv[kj * SST + dq + 3] = v.w;
    }

    {
        const int w    = t >> 5;
        const int lane = t & 31;
        #pragma unroll
        for (int rr = 0; rr < 4; rr++) {
            const int r = w * 4 + rr;
            float x0 = ls[r * SST + lane];
            float x1 = ls[r * SST + lane + 32];
            float x2 = ls[r * SST + lane + 64];
            float x3 = ls[r * SST + lane + 96];
            float mx = fmaxf(fmaxf(x0, x1), fmaxf(x2, x3));
            #pragma unroll
            for (int off = 16; off; off >>= 1)
                mx = fmaxf(mx, __shfl_xor_sync(0xffffffffu, mx, off));
            float e0 = (x0 <= -1e29f) ? 0.f : expf(x0 - mx);
            float e1 = (x1 <= -1e29f) ? 0.f : expf(x1 - mx);
            float e2 = (x2 <= -1e29f) ? 0.f : expf(x2 - mx);
            float e3 = (x3 <= -1e29f) ? 0.f : expf(x3 - mx);
            float s = e0 + e1 + e2 + e3;
            #pragma unroll
            for (int off = 16; off; off >>= 1)
                s += __shfl_xor_sync(0xffffffffu, s, off);
            const float inv = (s > 0.f) ? (1.f / s) : 0.f;
            ls[r * SST + lane]      = e0 * inv;
            ls[r * SST + lane + 32] = e1 * inv;
            ls[r * SST + lane + 64] = e2 * inv;
            ls[r * SST + lane + 96] = e3 * inv;
        }
    }
    __syncthreads();

    float o[4][4];
    #pragma unroll
    for (int i = 0; i < 4; i++)
        #pragma unroll
        for (int j = 0; j < 4; j++) o[i][j] = 0.f;

    for (int kj = 0; kj < NE; kj++) {
        float a[4], bb[4];
        #pragma unroll
        for (int i = 0; i < 4; i++) a[i]  = ls[(ty + 8 * i) * SST + kj];
        #pragma unroll
        for (int j = 0; j < 4; j++) bb[j] = kv[kj * SST + tx + 32 * j];
        #pragma unroll
        for (int i = 0; i < 4; i++)
            #pragma unroll
            for (int j = 0; j < 4; j++)
                o[i][j] = fmaf(a[i], bb[j], o[i][j]);
    }

    #pragma unroll
    for (int i = 0; i < 4; i++) {
        const int qi = ty + 8 * i;
        #pragma unroll
        for (int j = 0; j < 4; j++) {
            const int d = tx + 32 * j;
            const size_t idx = (size_t)(b * NQ + qi) * EMB + h * HD + d;
            const float ov = o[i][j];
            const __nv_bfloat16 hb = __float2bfloat16(ov);
            g_aoh[idx] = hb;
            g_aol[idx] = __float2bfloat16(ov - __bfloat162float(hb));
        }
    }
}

// ============================================================================
extern "C" void kernel_launch(void* const* d_in, const int* in_sizes, int n_in,
                              void* d_out, int out_size)
{
    const float *entities = nullptr, *W_in = nullptr, *W_out = nullptr,
                *b_out = nullptr;
    const void  *pre_mask = nullptr, *post_mask = nullptr;
    for (int i = 0; i < n_in; i++) {
        switch (in_sizes[i]) {
            case BS * NE * IND:   entities  = (const float*)d_in[i]; break;
            case BS * NQ * NE:    pre_mask  = d_in[i];               break;
            case BS * NQ:         post_mask = d_in[i];               break;
            case 3 * EMB * IND:   W_in      = (const float*)d_in[i]; break;
            case EMB * EMB:       W_out     = (const float*)d_in[i]; break;
            case EMB:             b_out     = (const float*)d_in[i]; break;
        }
    }
    float* out = (float*)d_out;

    cudaFuncSetAttribute(attn_kernel,
                         cudaFuncAttributeMaxDynamicSharedMemorySize, ATTN_SMEM);
    cudaFuncSetAttribute(mma_gemm_bf<IND, 0>,
                         cudaFuncAttributeMaxDynamicSharedMemorySize, GEMM_SMEM);
    cudaFuncSetAttribute(mma_gemm_bf<IND, 1>,
                         cudaFuncAttributeMaxDynamicSharedMemorySize, GEMM_SMEM);
    cudaFuncSetAttribute(mma_gemm_bf<EMB, 2>,
                         cudaFuncAttributeMaxDynamicSharedMemorySize, GEMM_SMEM);

    __nv_bfloat16 *eh, *el, *wih, *wil, *woh, *wol, *aoh, *aol;
    uint8_t *pre_dst, *post_dst;
    cudaGetSymbolAddress((void**)&eh,  g_eh);
    cudaGetSymbolAddress((void**)&el,  g_el);
    cudaGetSymbolAddress((void**)&wih, g_wih);
    cudaGetSymbolAddress((void**)&wil, g_wil);
    cudaGetSymbolAddress((void**)&woh, g_woh);
    cudaGetSymbolAddress((void**)&wol, g_wol);
    cudaGetSymbolAddress((void**)&aoh, g_aoh);
    cudaGetSymbolAddress((void**)&aol, g_aol);
    cudaGetSymbolAddress((void**)&pre_dst,  g_pre);
    cudaGetSymbolAddress((void**)&post_dst, g_post);

    // 0) normalize masks + pre-split operands
    sniff_kernel<<<1, 256>>>(pre_mask);
    cvt_mask_kernel<<<(BS * NQ * NE + 255) / 256, 256>>>(pre_mask, pre_dst,
                                                         BS * NQ * NE);
    cvt_mask_kernel<<<(BS * NQ + 255) / 256, 256>>>(post_mask, post_dst,
                                                    BS * NQ);
    split_kernel<<<(BS * NE * IND / 4 + 255) / 256, 256>>>(entities, eh, el,
                                                           BS * NE * IND / 4);
    split_kernel<<<(3 * EMB * IND / 4 + 255) / 256, 256>>>(W_in, wih, wil,
                                                           3 * EMB * IND / 4);
    split_kernel<<<(EMB * EMB / 4 + 255) / 256, 256>>>(W_out, woh, wol,
                                                       EMB * EMB / 4);

    // 1) K,V projection -> g_k, g_v
    mma_gemm_bf<IND, 0><<<dim3(8, BS), 256, GEMM_SMEM>>>(
        eh, el, wih + (size_t)EMB * IND, wil + (size_t)EMB * IND,
        nullptr, nullptr);

    // 2) Q projection -> g_q
    mma_gemm_bf<IND, 1><<<dim3(4, (BS * NQ) / 128), 256, GEMM_SMEM>>>(
        eh, el, wih, wil, nullptr, nullptr);

    // 3) masked multi-head attention -> g_aoh/g_aol (bf16 split)
    attn_kernel<<<dim3(BS, NH), 256, ATTN_SMEM>>>();

    // 4) output projection + bias + post_mask -> d_out
    mma_gemm_bf<EMB, 2><<<dim3(4, (BS * NQ) / 128), 256, GEMM_SMEM>>>(
        aoh, aol, woh, wol, out, b_out);
}

// round 11
// speedup vs baseline: 1.5211x; 1.3650x over previous
#include <cuda_runtime.h>
#include <cuda_fp16.h>
#include <stdint.h>
#include <math.h>

// Problem constants
#define BS   4096
#define NE   128
#define NQ   32
#define IND  256
#define EMB  512
#define NH   4
#define HD   128

// -------- scratch (static device globals; no runtime allocation) --------
__device__ float g_k [BS * NE * EMB];
__device__ float g_v [BS * NE * EMB];
__device__ float g_q [BS * NQ * EMB];
__device__ uint8_t g_pre [BS * NQ * NE];
__device__ uint8_t g_post[BS * NQ];
__device__ int     g_mask_kind;
// fp16 operands: activations hi-only (A-side), weights hi+lo (B-side)
__device__ __half g_eh [BS * NE * IND];
__device__ __half g_wih[3 * EMB * IND], g_wil[3 * EMB * IND];
__device__ __half g_woh[EMB * EMB],     g_wol[EMB * EMB];
__device__ __half g_aoh[BS * NQ * EMB];

// ============================================================================
// Mask dtype sniffer + normalizer (proven)
// ============================================================================
__global__ void sniff_kernel(const void* __restrict__ pre)
{
    __shared__ int s_hasF, s_hasHi;
    if (threadIdx.x == 0) { s_hasF = 0; s_hasHi = 0; }
    __syncthreads();
    const unsigned* w = (const unsigned*)pre;
    int hasF = 0, hasHi = 0;
    for (int i = threadIdx.x; i < 16384; i += blockDim.x) {
        const unsigned v = w[i];
        if (v == 0x3F800000u) hasF = 1;
        if (v & 0xFFFFFF00u)  hasHi = 1;
    }
    if (hasF)  atomicOr(&s_hasF, 1);
    if (hasHi) atomicOr(&s_hasHi, 1);
    __syncthreads();
    if (threadIdx.x == 0)
        g_mask_kind = s_hasF ? 2 : (s_hasHi ? 0 : 1);
}

__global__ void cvt_mask_kernel(const void* __restrict__ src,
                                uint8_t* __restrict__ dst, int n)
{
    const int i = blockIdx.x * blockDim.x + threadIdx.x;
    if (i >= n) return;
    const int k = g_mask_kind;
    uint8_t v;
    if (k == 0)      v = (((const uint8_t*)src)[i] != 0);
    else if (k == 1) v = (((const int*)src)[i] != 0);
    else             v = (((const float*)src)[i] != 0.f);
    dst[i] = v;
}

// ============================================================================
// fp32 -> fp16 conversions
// ============================================================================
__global__ void cvt_h_kernel(const float* __restrict__ src,
                             __half* __restrict__ h, int n4)
{
    const int i = blockIdx.x * blockDim.x + threadIdx.x;
    if (i >= n4) return;
    const float4 v = reinterpret_cast<const float4*>(src)[i];
    __half2 h0 = __floats2half2_rn(v.x, v.y);
    __half2 h1 = __floats2half2_rn(v.z, v.w);
    uint32_t* hp = reinterpret_cast<uint32_t*>(h);
    hp[2 * i]     = *reinterpret_cast<uint32_t*>(&h0);
    hp[2 * i + 1] = *reinterpret_cast<uint32_t*>(&h1);
}

__global__ void split_h_kernel(const float* __restrict__ src,
                               __half* __restrict__ h,
                               __half* __restrict__ l, int n4)
{
    const int i = blockIdx.x * blockDim.x + threadIdx.x;
    if (i >= n4) return;
    const float4 v = reinterpret_cast<const float4*>(src)[i];
    __half2 h0 = __floats2half2_rn(v.x, v.y);
    __half2 h1 = __floats2half2_rn(v.z, v.w);
    __half2 l0 = __floats2half2_rn(v.x - __half2float(h0.x),
                                   v.y - __half2float(h0.y));
    __half2 l1 = __floats2half2_rn(v.z - __half2float(h1.x),
                                   v.w - __half2float(h1.y));
    uint32_t* hp = reinterpret_cast<uint32_t*>(h);
    uint32_t* lp = reinterpret_cast<uint32_t*>(l);
    hp[2 * i]     = *reinterpret_cast<uint32_t*>(&h0);
    hp[2 * i + 1] = *reinterpret_cast<uint32_t*>(&h1);
    lp[2 * i]     = *reinterpret_cast<uint32_t*>(&l0);
    lp[2 * i + 1] = *reinterpret_cast<uint32_t*>(&l1);
}

// ============================================================================
// fp16 2-term GEMM: cp.async 3-stage pipeline + ldmatrix fragment loads.
//   C[M,N] = A[M,K] @ W[N,K]^T ~= Ah*Bh + Ah*Bl   (fp32 accum)
//   (dropped Al*B term ~2^-11 relative; norm rel-err ~3e-4 per GEMM)
// Tile 128x128, BK=32, 256 thr = 8 warps (2M x 4N), warp = 64x32.
// Stage = {Ah, Bh, Bl} 128x32 fp16 (8KB each); row r, 16B quad q at
//   r*64 + ((q ^ ((r>>1)&3))<<4)   (conflict-free for cp.async & ldmatrix)
// ============================================================================
#define STAGE_B 24576
#define GEMM_SMEM (3 * STAGE_B)

__device__ __forceinline__ void mma_f16(float* d, const uint32_t* a,
                                        const uint32_t* b)
{
    asm volatile(
        "mma.sync.aligned.m16n8k16.row.col.f32.f16.f16.f32 "
        "{%0,%1,%2,%3}, {%4,%5,%6,%7}, {%8,%9}, {%0,%1,%2,%3};"
        : "+f"(d[0]), "+f"(d[1]), "+f"(d[2]), "+f"(d[3])
        : "r"(a[0]), "r"(a[1]), "r"(a[2]), "r"(a[3]), "r"(b[0]), "r"(b[1]));
}

__device__ __forceinline__ void ldm_x4(uint32_t* r, uint32_t addr)
{
    asm volatile("ldmatrix.sync.aligned.m8n8.x4.shared.b16 {%0,%1,%2,%3}, [%4];"
                 : "=r"(r[0]), "=r"(r[1]), "=r"(r[2]), "=r"(r[3]) : "r"(addr));
}

__device__ __forceinline__ uint32_t smem_u32(const void* p) {
    uint32_t a;
    asm("{ .reg .u64 t; cvta.to.shared.u64 t, %1; cvt.u32.u64 %0, t; }"
        : "=r"(a) : "l"(p));
    return a;
}

__device__ __forceinline__ uint32_t swz(int r, int q) {
    return (uint32_t)(r * 64 + ((q ^ ((r >> 1) & 3)) << 4));
}

template<int KDIM, int MODE>
__global__ __launch_bounds__(256, 2)
void mma_gemm_h(const __half* __restrict__ Ah_g,
                const __half* __restrict__ Bh_g,
                const __half* __restrict__ Bl_g,
                float* __restrict__ Cout,
                const float* __restrict__ bias)
{
    constexpr int S = KDIM / 32;
    extern __shared__ char smem[];
    const uint32_t sb = smem_u32(smem);

    const int t    = threadIdx.x;
    const int lane = t & 31;
    const int wid  = t >> 5;
    const int wm   = wid >> 2;
    const int wn   = wid & 3;
    const int ntile = blockIdx.x;
    const int mtile = blockIdx.y;
    const int rq = lane >> 2;
    const int pq = lane & 3;

    // ldmatrix lane-group geometry (proven in R9)
    const int g  = lane >> 3;
    const int lr = lane & 7;
    const int arow_l = wm * 64 + ((g & 1) ? 8 : 0) + lr;
    const int aq_l   = g >> 1;
    const int brow_l = wn * 32 + ((g >= 2) ? 8 : 0) + lr;
    const int bq_l   = g & 1;

    // one stage = 1536 x 16B quads (Ah | Bh | Bl), 6 per thread
    auto issue = [&](int s, int buf) {
        #pragma unroll
        for (int i = 0; i < 6; i++) {
            const int idx = t + i * 256;
            const int arr = idx >> 9;          // 0=Ah 1=Bh 2=Bl
            const int rem = idx & 511;
            const int r   = rem >> 2;
            const int q   = rem & 3;
            const __half* gp;
            if (arr == 0) {
                const int gm = mtile * 128 + r;
                const int arow = (MODE == 1) ? ((gm >> 5) * NE + (gm & 31)) : gm;
                gp = Ah_g + (size_t)arow * KDIM + s * 32 + q * 8;
            } else {
                gp = (arr == 1 ? Bh_g : Bl_g)
                    + (size_t)(ntile * 128 + r) * KDIM + s * 32 + q * 8;
            }
            const uint32_t dst = sb + buf * STAGE_B + arr * 8192 + swz(r, q);
            asm volatile("cp.async.ca.shared.global [%0], [%1], 16;"
                         :: "r"(dst), "l"(gp));
        }
        asm volatile("cp.async.commit_group;" ::: "memory");
    };

    float acc[4][4][4];
    #pragma unroll
    for (int i = 0; i < 4; i++)
        #pragma unroll
        for (int j = 0; j < 4; j++)
            #pragma unroll
            for (int c = 0; c < 4; c++) acc[i][j][c] = 0.f;

    issue(0, 0);
    issue(1, 1);

    for (int s = 0; s < S; s++) {
        asm volatile("cp.async.wait_group 1;" ::: "memory");
        __syncthreads();
        if (s + 2 < S) issue(s + 2, (s + 2) % 3);
        else asm volatile("cp.async.commit_group;" ::: "memory");

        const uint32_t st = sb + (s % 3) * STAGE_B;  // Ah | Bh(+8K) | Bl(+16K)

        #pragma unroll
        for (int kh = 0; kh < 2; kh++) {
            uint32_t bh[4][2], bl[4][2];
            #pragma unroll
            for (int nfp = 0; nfp < 2; nfp++) {
                const uint32_t off = swz(brow_l + nfp * 16, 2 * kh + bq_l);
                uint32_t rh[4], rl[4];
                ldm_x4(rh, st + 8192 + off);
                ldm_x4(rl, st + 16384 + off);
                bh[2 * nfp][0] = rh[0]; bh[2 * nfp][1] = rh[1];
                bh[2 * nfp + 1][0] = rh[2]; bh[2 * nfp + 1][1] = rh[3];
                bl[2 * nfp][0] = rl[0]; bl[2 * nfp][1] = rl[1];
                bl[2 * nfp + 1][0] = rl[2]; bl[2 * nfp + 1][1] = rl[3];
            }
            #pragma unroll
            for (int mf = 0; mf < 4; mf++) {
                const uint32_t off = swz(arow_l + mf * 16, 2 * kh + aq_l);
                uint32_t ah[4];
                ldm_x4(ah, st + off);
                #pragma unroll
                for (int nf = 0; nf < 4; nf++) {
                    mma_f16(acc[mf][nf], ah, bh[nf]);
                    mma_f16(acc[mf][nf], ah, bl[nf]);
                }
            }
        }
    }
    asm volatile("cp.async.wait_group 0;" ::: "memory");

    // ---- epilogue ----
    #pragma unroll
    for (int mf = 0; mf < 4; mf++) {
        #pragma unroll
        for (int nf = 0; nf < 4; nf++) {
            const int r0 = mtile * 128 + wm * 64 + mf * 16 + rq;
            const int r1 = r0 + 8;
            const int gn = ntile * 128 + wn * 32 + nf * 8 + pq * 2;
            float2 v0 = make_float2(acc[mf][nf][0], acc[mf][nf][1]);
            float2 v1 = make_float2(acc[mf][nf][2], acc[mf][nf][3]);
            if (MODE == 0) {
                if (gn < EMB) {
                    *reinterpret_cast<float2*>(&g_k[(size_t)r0 * EMB + gn]) = v0;
                    *reinterpret_cast<float2*>(&g_k[(size_t)r1 * EMB + gn]) = v1;
                } else {
                    *reinterpret_cast<float2*>(&g_v[(size_t)r0 * EMB + gn - EMB]) = v0;
                    *reinterpret_cast<float2*>(&g_v[(size_t)r1 * EMB + gn - EMB]) = v1;
                }
            } else if (MODE == 1) {
                *reinterpret_cast<float2*>(&g_q[(size_t)r0 * EMB + gn]) = v0;
                *reinterpret_cast<float2*>(&g_q[(size_t)r1 * EMB + gn]) = v1;
            } else {
                const float2 bb = *reinterpret_cast<const float2*>(&bias[gn]);
                v0.x += bb.x; v0.y += bb.y;
                v1.x += bb.x; v1.y += bb.y;
                if (g_post[r0]) { v0.x = 0.f; v0.y = 0.f; }
                if (g_post[r1]) { v1.x = 0.f; v1.y = 0.f; }
                *reinterpret_cast<float2*>(&Cout[(size_t)r0 * EMB + gn]) = v0;
                *reinterpret_cast<float2*>(&Cout[(size_t)r1 * EMB + gn]) = v1;
            }
        }
    }
}

// ============================================================================
// Attention: one CTA per (batch, head), fp32 scalar; writes fp16 ao.
// ============================================================================
#define SST 129
#define ATTN_SMEM ((32 + 128 + 32) * SST * 4)

__global__ __launch_bounds__(256)
void attn_kernel()
{
    const int b = blockIdx.x;
    const int h = blockIdx.y;
    extern __shared__ float sm[];
    float* qs = sm;
    float* kv = sm + 32 * SST;
    float* ls = sm + (32 + 128) * SST;

    const int t  = threadIdx.x;
    const int tx = t & 31;
    const int ty = t >> 5;

    #pragma unroll
    for (int l = 0; l < 4; l++) {
        const int idx = t + l * 256;
        const int qi  = idx >> 5;
        const int dq  = (idx & 31) * 4;
        const float4 v = *reinterpret_cast<const float4*>(
            &g_q[(size_t)(b * NQ + qi) * EMB + h * HD + dq]);
        qs[qi * SST + dq + 0] = v.x; qs[qi * SST + dq + 1] = v.y;
        qs[qi * SST + dq + 2] = v.z; qs[qi * SST + dq + 3] = v.w;
    }
    #pragma unroll
    for (int l = 0; l < 16; l++) {
        const int idx = t + l * 256;
        const int kj  = idx >> 5;
        const int dq  = (idx & 31) * 4;
        const float4 v = *reinterpret_cast<const float4*>(
            &g_k[(size_t)(b * NE + kj) * EMB + h * HD + dq]);
        kv[kj * SST + dq + 0] = v.x; kv[kj * SST + dq + 1] = v.y;
        kv[kj * SST + dq + 2] = v.z; kv[kj * SST + dq + 3] = v.w;
    }
    __syncthreads();

    float acc[4][4];
    #pragma unroll
    for (int i = 0; i < 4; i++)
        #pragma unroll
        for (int j = 0; j < 4; j++) acc[i][j] = 0.f;

    for (int d = 0; d < HD; d++) {
        float a[4], bb[4];
        #pragma unroll
        for (int i = 0; i < 4; i++) a[i]  = qs[(ty + 8 * i) * SST + d];
        #pragma unroll
        for (int j = 0; j < 4; j++) bb[j] = kv[(tx + 32 * j) * SST + d];
        #pragma unroll
        for (int i = 0; i < 4; i++)
            #pragma unroll
            for (int j = 0; j < 4; j++)
                acc[i][j] = fmaf(a[i], bb[j], acc[i][j]);
    }

    const float inv_scale = 0.08838834764831845f;
    const uint8_t* pm = g_pre + (size_t)b * NQ * NE;
    #pragma unroll
    for (int i = 0; i < 4; i++) {
        const int qi = ty + 8 * i;
        #pragma unroll
        for (int j = 0; j < 4; j++) {
            const int kj = tx + 32 * j;
            ls[qi * SST + kj] = pm[qi * NE + kj] ? -1e30f : acc[i][j] * inv_scale;
        }
    }
    __syncthreads();

    #pragma unroll
    for (int l = 0; l < 16; l++) {
        const int idx = t + l * 256;
        const int kj  = idx >> 5;
        const int dq  = (idx & 31) * 4;
        const float4 v = *reinterpret_cast<const float4*>(
            &g_v[(size_t)(b * NE + kj) * EMB + h * HD + dq]);
        kv[kj * SST + dq + 0] = v.x; kv[kj * SST + dq + 1] = v.y;
        kv[kj * SST + dq + 2] = v.z; kv[kj * SST + dq + 3] = v.w;
    }

    {
        const int w    = t >> 5;
        const int lane = t & 31;
        #pragma unroll
        for (int rr = 0; rr < 4; rr++) {
            const int r = w * 4 + rr;
            float x0 = ls[r * SST + lane];
            float x1 = ls[r * SST + lane + 32];
            float x2 = ls[r * SST + lane + 64];
            float x3 = ls[r * SST + lane + 96];
            float mx = fmaxf(fmaxf(x0, x1), fmaxf(x2, x3));
            #pragma unroll
            for (int off = 16; off; off >>= 1)
                mx = fmaxf(mx, __shfl_xor_sync(0xffffffffu, mx, off));
            float e0 = (x0 <= -1e29f) ? 0.f : expf(x0 - mx);
            float e1 = (x1 <= -1e29f) ? 0.f : expf(x1 - mx);
            float e2 = (x2 <= -1e29f) ? 0.f : expf(x2 - mx);
            float e3 = (x3 <= -1e29f) ? 0.f : expf(x3 - mx);
            float s = e0 + e1 + e2 + e3;
            #pragma unroll
            for (int off = 16; off; off >>= 1)
                s += __shfl_xor_sync(0xffffffffu, s, off);
            const float inv = (s > 0.f) ? (1.f / s) : 0.f;
            ls[r * SST + lane]      = e0 * inv;
            ls[r * SST + lane + 32] = e1 * inv;
            ls[r * SST + lane + 64] = e2 * inv;
            ls[r * SST + lane + 96] = e3 * inv;
        }
    }
    __syncthreads();

    float o[4][4];
    #pragma unroll
    for (int i = 0; i < 4; i++)
        #pragma unroll
        for (int j = 0; j < 4; j++) o[i][j] = 0.f;

    for (int kj = 0; kj < NE; kj++) {
        float a[4], bb[4];
        #pragma unroll
        for (int i = 0; i < 4; i++) a[i]  = ls[(ty + 8 * i) * SST + kj];
        #pragma unroll
        for (int j = 0; j < 4; j++) bb[j] = kv[kj * SST + tx + 32 * j];
        #pragma unroll
        for (int i = 0; i < 4; i++)
            #pragma unroll
            for (int j = 0; j < 4; j++)
                o[i][j] = fmaf(a[i], bb[j], o[i][j]);
    }

    #pragma unroll
    for (int i = 0; i < 4; i++) {
        const int qi = ty + 8 * i;
        #pragma unroll
        for (int j = 0; j < 4; j++) {
            const int d = tx + 32 * j;
            g_aoh[(size_t)(b * NQ + qi) * EMB + h * HD + d] =
                __float2half_rn(o[i][j]);
        }
    }
}

// ============================================================================
extern "C" void kernel_launch(void* const* d_in, const int* in_sizes, int n_in,
                              void* d_out, int out_size)
{
    const float *entities = nullptr, *W_in = nullptr, *W_out = nullptr,
                *b_out = nullptr;
    const void  *pre_mask = nullptr, *post_mask = nullptr;
    for (int i = 0; i < n_in; i++) {
        switch (in_sizes[i]) {
            case BS * NE * IND:   entities  = (const float*)d_in[i]; break;
            case BS * NQ * NE:    pre_mask  = d_in[i];               break;
            case BS * NQ:         post_mask = d_in[i];               break;
            case 3 * EMB * IND:   W_in      = (const float*)d_in[i]; break;
            case EMB * EMB:       W_out     = (const float*)d_in[i]; break;
            case EMB:             b_out     = (const float*)d_in[i]; break;
        }
    }
    float* out = (float*)d_out;

    cudaFuncSetAttribute(attn_kernel,
                         cudaFuncAttributeMaxDynamicSharedMemorySize, ATTN_SMEM);
    cudaFuncSetAttribute(mma_gemm_h<IND, 0>,
                         cudaFuncAttributeMaxDynamicSharedMemorySize, GEMM_SMEM);
    cudaFuncSetAttribute(mma_gemm_h<IND, 1>,
                         cudaFuncAttributeMaxDynamicSharedMemorySize, GEMM_SMEM);
    cudaFuncSetAttribute(mma_gemm_h<EMB, 2>,
                         cudaFuncAttributeMaxDynamicSharedMemorySize, GEMM_SMEM);

    __half *eh, *wih, *wil, *woh, *wol, *aoh;
    uint8_t *pre_dst, *post_dst;
    cudaGetSymbolAddress((void**)&eh,  g_eh);
    cudaGetSymbolAddress((void**)&wih, g_wih);
    cudaGetSymbolAddress((void**)&wil, g_wil);
    cudaGetSymbolAddress((void**)&woh, g_woh);
    cudaGetSymbolAddress((void**)&wol, g_wol);
    cudaGetSymbolAddress((void**)&aoh, g_aoh);
    cudaGetSymbolAddress((void**)&pre_dst,  g_pre);
    cudaGetSymbolAddress((void**)&post_dst, g_post);

    // 0) normalize masks + convert operands
    sniff_kernel<<<1, 256>>>(pre_mask);
    cvt_mask_kernel<<<(BS * NQ * NE + 255) / 256, 256>>>(pre_mask, pre_dst,
                                                         BS * NQ * NE);
    cvt_mask_kernel<<<(BS * NQ + 255) / 256, 256>>>(post_mask, post_dst,
                                                    BS * NQ);
    cvt_h_kernel<<<(BS * NE * IND / 4 + 255) / 256, 256>>>(
        entities, eh, BS * NE * IND / 4);
    split_h_kernel<<<(3 * EMB * IND / 4 + 255) / 256, 256>>>(
        W_in, wih, wil, 3 * EMB * IND / 4);
    split_h_kernel<<<(EMB * EMB / 4 + 255) / 256, 256>>>(
        W_out, woh, wol, EMB * EMB / 4);

    // 1) K,V projection -> g_k, g_v
    mma_gemm_h<IND, 0><<<dim3(8, BS), 256, GEMM_SMEM>>>(
        eh, wih + (size_t)EMB * IND, wil + (size_t)EMB * IND,
        nullptr, nullptr);

    // 2) Q projection -> g_q
    mma_gemm_h<IND, 1><<<dim3(4, (BS * NQ) / 128), 256, GEMM_SMEM>>>(
        eh, wih, wil, nullptr, nullptr);

    // 3) masked multi-head attention -> g_aoh (fp16)
    attn_kernel<<<dim3(BS, NH), 256, ATTN_SMEM>>>();

    // 4) output projection + bias + post_mask -> d_out
    mma_gemm_h<EMB, 2><<<dim3(4, (BS * NQ) / 128), 256, GEMM_SMEM>>>(
        aoh, woh, wol, out, b_out);
}

// round 12
// speedup vs baseline: 2.0725x; 1.3625x over previous
#include <cuda_runtime.h>
#include <cuda_fp16.h>
#include <stdint.h>
#include <math.h>

// Problem constants
#define BS   4096
#define NE   128
#define NQ   32
#define IND  256
#define EMB  512
#define NH   4
#define HD   128

// -------- scratch (static device globals; no runtime allocation) --------
__device__ uint8_t g_pre [BS * NQ * NE];
__device__ uint8_t g_post[BS * NQ];
__device__ int     g_mask_kind;
// fp16 operands
__device__ __half g_eh [BS * NE * IND];
__device__ __half g_wih[3 * EMB * IND], g_wil[3 * EMB * IND];
__device__ __half g_woh[EMB * EMB],     g_wol[EMB * EMB];
__device__ __half g_qh [BS * NQ * EMB];        // q  [b*NQ+qi][512]
__device__ __half g_kh [BS * NE * EMB];        // k  [b*NE+e][512]
__device__ __half g_vt [BS * EMB * NE];        // vT [b][d(512)][e(128)]
__device__ __half g_aoh[BS * NQ * EMB];        // attn out fp16

// ============================================================================
// Mask dtype sniffer + normalizer (proven)
// ============================================================================
__global__ void sniff_kernel(const void* __restrict__ pre)
{
    __shared__ int s_hasF, s_hasHi;
    if (threadIdx.x == 0) { s_hasF = 0; s_hasHi = 0; }
    __syncthreads();
    const unsigned* w = (const unsigned*)pre;
    int hasF = 0, hasHi = 0;
    for (int i = threadIdx.x; i < 16384; i += blockDim.x) {
        const unsigned v = w[i];
        if (v == 0x3F800000u) hasF = 1;
        if (v & 0xFFFFFF00u)  hasHi = 1;
    }
    if (hasF)  atomicOr(&s_hasF, 1);
    if (hasHi) atomicOr(&s_hasHi, 1);
    __syncthreads();
    if (threadIdx.x == 0)
        g_mask_kind = s_hasF ? 2 : (s_hasHi ? 0 : 1);
}

__global__ void cvt_mask_kernel(const void* __restrict__ src,
                                uint8_t* __restrict__ dst, int n)
{
    const int i = blockIdx.x * blockDim.x + threadIdx.x;
    if (i >= n) return;
    const int k = g_mask_kind;
    uint8_t v;
    if (k == 0)      v = (((const uint8_t*)src)[i] != 0);
    else if (k == 1) v = (((const int*)src)[i] != 0);
    else             v = (((const float*)src)[i] != 0.f);
    dst[i] = v;
}

// ============================================================================
// fp32 -> fp16 conversions
// ============================================================================
__global__ void cvt_h_kernel(const float* __restrict__ src,
                             __half* __restrict__ h, int n4)
{
    const int i = blockIdx.x * blockDim.x + threadIdx.x;
    if (i >= n4) return;
    const float4 v = reinterpret_cast<const float4*>(src)[i];
    __half2 h0 = __floats2half2_rn(v.x, v.y);
    __half2 h1 = __floats2half2_rn(v.z, v.w);
    uint32_t* hp = reinterpret_cast<uint32_t*>(h);
    hp[2 * i]     = *reinterpret_cast<uint32_t*>(&h0);
    hp[2 * i + 1] = *reinterpret_cast<uint32_t*>(&h1);
}

__global__ void split_h_kernel(const float* __restrict__ src,
                               __half* __restrict__ h,
                               __half* __restrict__ l, int n4)
{
    const int i = blockIdx.x * blockDim.x + threadIdx.x;
    if (i >= n4) return;
    const float4 v = reinterpret_cast<const float4*>(src)[i];
    __half2 h0 = __floats2half2_rn(v.x, v.y);
    __half2 h1 = __floats2half2_rn(v.z, v.w);
    __half2 l0 = __floats2half2_rn(v.x - __half2float(h0.x),
                                   v.y - __half2float(h0.y));
    __half2 l1 = __floats2half2_rn(v.z - __half2float(h1.x),
                                   v.w - __half2float(h1.y));
    uint32_t* hp = reinterpret_cast<uint32_t*>(h);
    uint32_t* lp = reinterpret_cast<uint32_t*>(l);
    hp[2 * i]     = *reinterpret_cast<uint32_t*>(&h0);
    hp[2 * i + 1] = *reinterpret_cast<uint32_t*>(&h1);
    lp[2 * i]     = *reinterpret_cast<uint32_t*>(&l0);
    lp[2 * i + 1] = *reinterpret_cast<uint32_t*>(&l1);
}

// ============================================================================
// common mma / ldmatrix helpers (proven R9/R11)
// ============================================================================
__device__ __forceinline__ void mma_f16(float* d, const uint32_t* a,
                                        const uint32_t* b)
{
    asm volatile(
        "mma.sync.aligned.m16n8k16.row.col.f32.f16.f16.f32 "
        "{%0,%1,%2,%3}, {%4,%5,%6,%7}, {%8,%9}, {%0,%1,%2,%3};"
        : "+f"(d[0]), "+f"(d[1]), "+f"(d[2]), "+f"(d[3])
        : "r"(a[0]), "r"(a[1]), "r"(a[2]), "r"(a[3]), "r"(b[0]), "r"(b[1]));
}

__device__ __forceinline__ void ldm_x4(uint32_t* r, uint32_t addr)
{
    asm volatile("ldmatrix.sync.aligned.m8n8.x4.shared.b16 {%0,%1,%2,%3}, [%4];"
                 : "=r"(r[0]), "=r"(r[1]), "=r"(r[2]), "=r"(r[3]) : "r"(addr));
}

__device__ __forceinline__ uint32_t smem_u32(const void* p) {
    uint32_t a;
    asm("{ .reg .u64 t; cvta.to.shared.u64 t, %1; cvt.u32.u64 %0, t; }"
        : "=r"(a) : "l"(p));
    return a;
}

// 64B-row swizzle (GEMM tiles: 32 fp16/row)
__device__ __forceinline__ uint32_t swz(int r, int q) {
    return (uint32_t)(r * 64 + ((q ^ ((r >> 1) & 3)) << 4));
}
// 256B-row swizzle (attention tiles: 128 fp16/row)
__device__ __forceinline__ uint32_t swA(int r, int q) {
    return (uint32_t)(r * 256 + ((q ^ (r & 7)) << 4));
}

// ============================================================================
// fp16 2-term GEMM (R11-proven core): C = A@W^T ~= Ah*Bh + Ah*Bl, fp32 accum
// MODE 0: KV -> g_kh (fp16) / g_vt (fp16, transposed)
// MODE 1: Q  -> g_qh (fp16)     MODE 2: out-proj -> fp32 + bias + post-mask
// ============================================================================
#define STAGE_B 24576
#define GEMM_SMEM (3 * STAGE_B)

template<int KDIM, int MODE>
__global__ __launch_bounds__(256, 2)
void mma_gemm_h(const __half* __restrict__ Ah_g,
                const __half* __restrict__ Bh_g,
                const __half* __restrict__ Bl_g,
                float* __restrict__ Cout,
                const float* __restrict__ bias)
{
    constexpr int S = KDIM / 32;
    extern __shared__ char smem[];
    const uint32_t sb = smem_u32(smem);

    const int t    = threadIdx.x;
    const int lane = t & 31;
    const int wid  = t >> 5;
    const int wm   = wid >> 2;
    const int wn   = wid & 3;
    const int ntile = blockIdx.x;
    const int mtile = blockIdx.y;
    const int rq = lane >> 2;
    const int pq = lane & 3;

    const int g  = lane >> 3;
    const int lr = lane & 7;
    const int arow_l = wm * 64 + ((g & 1) ? 8 : 0) + lr;
    const int aq_l   = g >> 1;
    const int brow_l = wn * 32 + ((g >= 2) ? 8 : 0) + lr;
    const int bq_l   = g & 1;

    auto issue = [&](int s, int buf) {
        #pragma unroll
        for (int i = 0; i < 6; i++) {
            const int idx = t + i * 256;
            const int arr = idx >> 9;          // 0=Ah 1=Bh 2=Bl
            const int rem = idx & 511;
            const int r   = rem >> 2;
            const int q   = rem & 3;
            const __half* gp;
            if (arr == 0) {
                const int gm = mtile * 128 + r;
                const int arow = (MODE == 1) ? ((gm >> 5) * NE + (gm & 31)) : gm;
                gp = Ah_g + (size_t)arow * KDIM + s * 32 + q * 8;
            } else {
                gp = (arr == 1 ? Bh_g : Bl_g)
                    + (size_t)(ntile * 128 + r) * KDIM + s * 32 + q * 8;
            }
            const uint32_t dst = sb + buf * STAGE_B + arr * 8192 + swz(r, q);
            asm volatile("cp.async.ca.shared.global [%0], [%1], 16;"
                         :: "r"(dst), "l"(gp));
        }
        asm volatile("cp.async.commit_group;" ::: "memory");
    };

    float acc[4][4][4];
    #pragma unroll
    for (int i = 0; i < 4; i++)
        #pragma unroll
        for (int j = 0; j < 4; j++)
            #pragma unroll
            for (int c = 0; c < 4; c++) acc[i][j][c] = 0.f;

    issue(0, 0);
    issue(1, 1);

    for (int s = 0; s < S; s++) {
        asm volatile("cp.async.wait_group 1;" ::: "memory");
        __syncthreads();
        if (s + 2 < S) issue(s + 2, (s + 2) % 3);
        else asm volatile("cp.async.commit_group;" ::: "memory");

        const uint32_t st = sb + (s % 3) * STAGE_B;

        #pragma unroll
        for (int kh = 0; kh < 2; kh++) {
            uint32_t bh[4][2], bl[4][2];
            #pragma unroll
            for (int nfp = 0; nfp < 2; nfp++) {
                const uint32_t off = swz(brow_l + nfp * 16, 2 * kh + bq_l);
                uint32_t rh[4], rl[4];
                ldm_x4(rh, st + 8192 + off);
                ldm_x4(rl, st + 16384 + off);
                bh[2 * nfp][0] = rh[0]; bh[2 * nfp][1] = rh[1];
                bh[2 * nfp + 1][0] = rh[2]; bh[2 * nfp + 1][1] = rh[3];
                bl[2 * nfp][0] = rl[0]; bl[2 * nfp][1] = rl[1];
                bl[2 * nfp + 1][0] = rl[2]; bl[2 * nfp + 1][1] = rl[3];
            }
            #pragma unroll
            for (int mf = 0; mf < 4; mf++) {
                const uint32_t off = swz(arow_l + mf * 16, 2 * kh + aq_l);
                uint32_t ah[4];
                ldm_x4(ah, st + off);
                #pragma unroll
                for (int nf = 0; nf < 4; nf++) {
                    mma_f16(acc[mf][nf], ah, bh[nf]);
                    mma_f16(acc[mf][nf], ah, bl[nf]);
                }
            }
        }
    }
    asm volatile("cp.async.wait_group 0;" ::: "memory");

    // ---- epilogue ----
    #pragma unroll
    for (int mf = 0; mf < 4; mf++) {
        #pragma unroll
        for (int nf = 0; nf < 4; nf++) {
            const int r0 = mtile * 128 + wm * 64 + mf * 16 + rq;
            const int r1 = r0 + 8;
            const int gn = ntile * 128 + wn * 32 + nf * 8 + pq * 2;
            float2 v0 = make_float2(acc[mf][nf][0], acc[mf][nf][1]);
            float2 v1 = make_float2(acc[mf][nf][2], acc[mf][nf][3]);
            if (MODE == 0) {
                if (gn < EMB) {
                    *reinterpret_cast<__half2*>(&g_kh[(size_t)r0 * EMB + gn]) =
                        __floats2half2_rn(v0.x, v0.y);
                    *reinterpret_cast<__half2*>(&g_kh[(size_t)r1 * EMB + gn]) =
                        __floats2half2_rn(v1.x, v1.y);
                } else {
                    const int d  = gn - EMB;
                    const int bb = r0 >> 7;
                    const int e0 = r0 & 127;
                    __half* vt = g_vt + (size_t)bb * EMB * NE;
                    vt[(size_t)d * NE + e0]           = __float2half_rn(v0.x);
                    vt[(size_t)(d + 1) * NE + e0]     = __float2half_rn(v0.y);
                    vt[(size_t)d * NE + e0 + 8]       = __float2half_rn(v1.x);
                    vt[(size_t)(d + 1) * NE + e0 + 8] = __float2half_rn(v1.y);
                }
            } else if (MODE == 1) {
                *reinterpret_cast<__half2*>(&g_qh[(size_t)r0 * EMB + gn]) =
                    __floats2half2_rn(v0.x, v0.y);
                *reinterpret_cast<__half2*>(&g_qh[(size_t)r1 * EMB + gn]) =
                    __floats2half2_rn(v1.x, v1.y);
            } else {
                const float2 bb = *reinterpret_cast<const float2*>(&bias[gn]);
                v0.x += bb.x; v0.y += bb.y;
                v1.x += bb.x; v1.y += bb.y;
                if (g_post[r0]) { v0.x = 0.f; v0.y = 0.f; }
                if (g_post[r1]) { v1.x = 0.f; v1.y = 0.f; }
                *reinterpret_cast<float2*>(&Cout[(size_t)r0 * EMB + gn]) = v0;
                *reinterpret_cast<float2*>(&Cout[(size_t)r1 * EMB + gn]) = v1;
            }
        }
    }
}

// ============================================================================
// Tensorized attention: one CTA per (b, h), 256 thr = 8 warps.
// S = Q@K^T via mma (warp w owns n-cols w*16..w*16+15), fp32 logits smem,
// proven shuffle softmax, P re-quantized fp16 into Q's smem, O = P@V via mma
// (V pre-transposed by the KV GEMM so only non-trans ldmatrix is needed).
// smem: qs/ps 8KB @0 | ks 32KB @8K | vs 32KB @40K | ls fp32 32x132 @72K
// ============================================================================
#define ATT_Q 0
#define ATT_K 8192
#define ATT_V 40960
#define ATT_L 73728
#define ATTN_SMEM (73728 + 32 * 132 * 4)   // 90624

__global__ __launch_bounds__(256, 2)
void attn_mma_kernel()
{
    const int b = blockIdx.x;
    const int h = blockIdx.y;
    extern __shared__ char sm[];
    const uint32_t sb = smem_u32(sm);

    const int t    = threadIdx.x;
    const int lane = t & 31;
    const int w    = t >> 5;

    // ---- async load q(32x128), k(128x128), v^T(128x128) fp16, swizzled ----
    #pragma unroll
    for (int i = 0; i < 2; i++) {                 // q: 512 quads
        const int idx = t + i * 256;
        const int r = idx >> 4, q = idx & 15;
        const __half* gp = g_qh + (size_t)(b * NQ + r) * EMB + h * HD + q * 8;
        asm volatile("cp.async.ca.shared.global [%0], [%1], 16;"
                     :: "r"(sb + ATT_Q + swA(r, q)), "l"(gp));
    }
    #pragma unroll
    for (int i = 0; i < 8; i++) {                 // k: 2048 quads
        const int idx = t + i * 256;
        const int r = idx >> 4, q = idx & 15;
        const __half* gp = g_kh + (size_t)(b * NE + r) * EMB + h * HD + q * 8;
        asm volatile("cp.async.ca.shared.global [%0], [%1], 16;"
                     :: "r"(sb + ATT_K + swA(r, q)), "l"(gp));
    }
    #pragma unroll
    for (int i = 0; i < 8; i++) {                 // v^T: 2048 quads
        const int idx = t + i * 256;
        const int r = idx >> 4, q = idx & 15;
        const __half* gp = g_vt + ((size_t)b * EMB + h * HD + r) * NE + q * 8;
        asm volatile("cp.async.ca.shared.global [%0], [%1], 16;"
                     :: "r"(sb + ATT_V + swA(r, q)), "l"(gp));
    }
    asm volatile("cp.async.commit_group;" ::: "memory");
    asm volatile("cp.async.wait_group 0;" ::: "memory");
    __syncthreads();

    // ldmatrix geometry (proven)
    const int g  = lane >> 3;
    const int lr = lane & 7;
    const int arow = ((g & 1) ? 8 : 0) + lr;   // + mf*16
    const int aq   = g >> 1;
    const int brow = w * 16 + ((g >= 2) ? 8 : 0) + lr;
    const int bq   = g & 1;
    const int rq = lane >> 2;
    const int pq = lane & 3;

    // ---- S = q @ k^T : warp w covers key-cols w*16..w*16+15 ----
    float acc[2][2][4];
    #pragma unroll
    for (int i = 0; i < 2; i++)
        #pragma unroll
        for (int j = 0; j < 2; j++)
            #pragma unroll
            for (int c = 0; c < 4; c++) acc[i][j][c] = 0.f;

    #pragma unroll
    for (int kf = 0; kf < 8; kf++) {
        uint32_t a0[4], a1[4], bb[4];
        ldm_x4(a0, sb + ATT_Q + swA(arow,      2 * kf + aq));
        ldm_x4(a1, sb + ATT_Q + swA(arow + 16, 2 * kf + aq));
        ldm_x4(bb, sb + ATT_K + swA(brow,      2 * kf + bq));
        mma_f16(acc[0][0], a0, bb);     mma_f16(acc[0][1], a0, bb + 2);
        mma_f16(acc[1][0], a1, bb);     mma_f16(acc[1][1], a1, bb + 2);
    }

    // ---- masked scaled logits -> ls (fp32) ----
    const float inv_scale = 0.08838834764831845f;   // 1/sqrt(128)
    float* ls = reinterpret_cast<float*>(sm + ATT_L);
    const uint8_t* pm = g_pre + (size_t)b * NQ * NE;
    #pragma unroll
    for (int mf = 0; mf < 2; mf++) {
        #pragma unroll
        for (int nf = 0; nf < 2; nf++) {
            const int row0 = mf * 16 + rq;
            const int row1 = row0 + 8;
            const int col  = w * 16 + nf * 8 + pq * 2;
            ls[row0 * 132 + col]     = pm[row0 * NE + col]     ? -1e30f : acc[mf][nf][0] * inv_scale;
            ls[row0 * 132 + col + 1] = pm[row0 * NE + col + 1] ? -1e30f : acc[mf][nf][1] * inv_scale;
            ls[row1 * 132 + col]     = pm[row1 * NE + col]     ? -1e30f : acc[mf][nf][2] * inv_scale;
            ls[row1 * 132 + col + 1] = pm[row1 * NE + col + 1] ? -1e30f : acc[mf][nf][3] * inv_scale;
        }
    }
    __syncthreads();

    // ---- softmax (proven shuffle code; warp w -> rows 4w..4w+3), P -> fp16
    //      into the q smem region (q no longer needed) ----
    char* psb = sm + ATT_Q;
    #pragma unroll
    for (int rr = 0; rr < 4; rr++) {
        const int r = w * 4 + rr;
        float x0 = ls[r * 132 + lane];
        float x1 = ls[r * 132 + lane + 32];
        float x2 = ls[r * 132 + lane + 64];
        float x3 = ls[r * 132 + lane + 96];
        float mx = fmaxf(fmaxf(x0, x1), fmaxf(x2, x3));
        #pragma unroll
        for (int off = 16; off; off >>= 1)
            mx = fmaxf(mx, __shfl_xor_sync(0xffffffffu, mx, off));
        float e0 = (x0 <= -1e29f) ? 0.f : expf(x0 - mx);
        float e1 = (x1 <= -1e29f) ? 0.f : expf(x1 - mx);
        float e2 = (x2 <= -1e29f) ? 0.f : expf(x2 - mx);
        float e3 = (x3 <= -1e29f) ? 0.f : expf(x3 - mx);
        float s = e0 + e1 + e2 + e3;
        #pragma unroll
        for (int off = 16; off; off >>= 1)
            s += __shfl_xor_sync(0xffffffffu, s, off);
        const float inv = (s > 0.f) ? (1.f / s) : 0.f;
        const int c0 = lane, c1 = lane + 32, c2 = lane + 64, c3 = lane + 96;
        *reinterpret_cast<__half*>(psb + swA(r, c0 >> 3) + (c0 & 7) * 2) = __float2half_rn(e0 * inv);
        *reinterpret_cast<__half*>(psb + swA(r, c1 >> 3) + (c1 & 7) * 2) = __float2half_rn(e1 * inv);
        *reinterpret_cast<__half*>(psb + swA(r, c2 >> 3) + (c2 & 7) * 2) = __float2half_rn(e2 * inv);
        *reinterpret_cast<__half*>(psb + swA(r, c3 >> 3) + (c3 & 7) * 2) = __float2half_rn(e3 * inv);
    }
    __syncthreads();

    // ---- O = P @ V : warp w covers hd-cols w*16..w*16+15 ----
    float o[2][2][4];
    #pragma unroll
    for (int i = 0; i < 2; i++)
        #pragma unroll
        for (int j = 0; j < 2; j++)
            #pragma unroll
            for (int c = 0; c < 4; c++) o[i][j][c] = 0.f;

    #pragma unroll
    for (int kf = 0; kf < 8; kf++) {
        uint32_t a0[4], a1[4], bb[4];
        ldm_x4(a0, sb + ATT_Q + swA(arow,      2 * kf + aq));
        ldm_x4(a1, sb + ATT_Q + swA(arow + 16, 2 * kf + aq));
        ldm_x4(bb, sb + ATT_V + swA(brow,      2 * kf + bq));
        mma_f16(o[0][0], a0, bb);      mma_f16(o[0][1], a0, bb + 2);
        mma_f16(o[1][0], a1, bb);      mma_f16(o[1][1], a1, bb + 2);
    }

    // ---- write ao fp16 ----
    #pragma unroll
    for (int mf = 0; mf < 2; mf++) {
        #pragma unroll
        for (int nf = 0; nf < 2; nf++) {
            const int row0 = mf * 16 + rq;
            const int row1 = row0 + 8;
            const int col  = w * 16 + nf * 8 + pq * 2;
            *reinterpret_cast<__half2*>(
                &g_aoh[(size_t)(b * NQ + row0) * EMB + h * HD + col]) =
                __floats2half2_rn(o[mf][nf][0], o[mf][nf][1]);
            *reinterpret_cast<__half2*>(
                &g_aoh[(size_t)(b * NQ + row1) * EMB + h * HD + col]) =
                __floats2half2_rn(o[mf][nf][2], o[mf][nf][3]);
        }
    }
}

// ============================================================================
extern "C" void kernel_launch(void* const* d_in, const int* in_sizes, int n_in,
                              void* d_out, int out_size)
{
    const float *entities = nullptr, *W_in = nullptr, *W_out = nullptr,
                *b_out = nullptr;
    const void  *pre_mask = nullptr, *post_mask = nullptr;
    for (int i = 0; i < n_in; i++) {
        switch (in_sizes[i]) {
            case BS * NE * IND:   entities  = (const float*)d_in[i]; break;
            case BS * NQ * NE:    pre_mask  = d_in[i];               break;
            case BS * NQ:         post_mask = d_in[i];               break;
            case 3 * EMB * IND:   W_in      = (const float*)d_in[i]; break;
            case EMB * EMB:       W_out     = (const float*)d_in[i]; break;
            case EMB:             b_out     = (const float*)d_in[i]; break;
        }
    }
    float* out = (float*)d_out;

    cudaFuncSetAttribute(attn_mma_kernel,
                         cudaFuncAttributeMaxDynamicSharedMemorySize, ATTN_SMEM);
    cudaFuncSetAttribute(mma_gemm_h<IND, 0>,
                         cudaFuncAttributeMaxDynamicSharedMemorySize, GEMM_SMEM);
    cudaFuncSetAttribute(mma_gemm_h<IND, 1>,
                         cudaFuncAttributeMaxDynamicSharedMemorySize, GEMM_SMEM);
    cudaFuncSetAttribute(mma_gemm_h<EMB, 2>,
                         cudaFuncAttributeMaxDynamicSharedMemorySize, GEMM_SMEM);

    __half *eh, *wih, *wil, *woh, *wol, *aoh;
    uint8_t *pre_dst, *post_dst;
    cudaGetSymbolAddress((void**)&eh,  g_eh);
    cudaGetSymbolAddress((void**)&wih, g_wih);
    cudaGetSymbolAddress((void**)&wil, g_wil);
    cudaGetSymbolAddress((void**)&woh, g_woh);
    cudaGetSymbolAddress((void**)&wol, g_wol);
    cudaGetSymbolAddress((void**)&aoh, g_aoh);
    cudaGetSymbolAddress((void**)&pre_dst,  g_pre);
    cudaGetSymbolAddress((void**)&post_dst, g_post);

    // 0) normalize masks + convert operands
    sniff_kernel<<<1, 256>>>(pre_mask);
    cvt_mask_kernel<<<(BS * NQ * NE + 255) / 256, 256>>>(pre_mask, pre_dst,
                                                         BS * NQ * NE);
    cvt_mask_kernel<<<(BS * NQ + 255) / 256, 256>>>(post_mask, post_dst,
                                                    BS * NQ);
    cvt_h_kernel<<<(BS * NE * IND / 4 + 255) / 256, 256>>>(
        entities, eh, BS * NE * IND / 4);
    split_h_kernel<<<(3 * EMB * IND / 4 + 255) / 256, 256>>>(
        W_in, wih, wil, 3 * EMB * IND / 4);
    split_h_kernel<<<(EMB * EMB / 4 + 255) / 256, 256>>>(
        W_out, woh, wol, EMB * EMB / 4);

    // 1) K,V projection -> g_kh (fp16), g_vt (fp16 transposed)
    mma_gemm_h<IND, 0><<<dim3(8, BS), 256, GEMM_SMEM>>>(
        eh, wih + (size_t)EMB * IND, wil + (size_t)EMB * IND,
        nullptr, nullptr);

    // 2) Q projection -> g_qh (fp16)
    mma_gemm_h<IND, 1><<<dim3(4, (BS * NQ) / 128), 256, GEMM_SMEM>>>(
        eh, wih, wil, nullptr, nullptr);

    // 3) tensorized masked attention -> g_aoh (fp16)
    attn_mma_kernel<<<dim3(BS, NH), 256, ATTN_SMEM>>>();

    // 4) output projection + bias + post_mask -> d_out
    mma_gemm_h<EMB, 2><<<dim3(4, (BS * NQ) / 128), 256, GEMM_SMEM>>>(
        aoh, woh, wol, out, b_out);
}

// round 14
// speedup vs baseline: 2.7388x; 1.3215x over previous
#include <cuda_runtime.h>
#include <cuda_fp16.h>
#include <stdint.h>
#include <math.h>

// Problem constants
#define BS   4096
#define NE   128
#define NQ   32
#define IND  256
#define EMB  512
#define NH   4
#define HD   128

// -------- scratch (static device globals; no runtime allocation) --------
__device__ uint8_t g_pre [BS * NQ * NE];
__device__ uint8_t g_post[BS * NQ];
__device__ int     g_mask_kind;
// fp16 operands (single-term: hi only everywhere)
__device__ __half g_eh [BS * NE * IND];
__device__ __half g_wih[3 * EMB * IND];
__device__ __half g_woh[EMB * EMB];
__device__ __half g_qh [BS * NQ * EMB];        // q  [b*NQ+qi][512]
__device__ __half g_kh [BS * NE * EMB];        // k  [b*NE+e][512]
__device__ __half g_vt [BS * EMB * NE];        // vT [b][d(512)][e(128)]
__device__ __half g_aoh[BS * NQ * EMB];        // attn out fp16

// ============================================================================
// Mask dtype sniffer + normalizer (proven)
// ============================================================================
__global__ void sniff_kernel(const void* __restrict__ pre)
{
    __shared__ int s_hasF, s_hasHi;
    if (threadIdx.x == 0) { s_hasF = 0; s_hasHi = 0; }
    __syncthreads();
    const unsigned* w = (const unsigned*)pre;
    int hasF = 0, hasHi = 0;
    for (int i = threadIdx.x; i < 16384; i += blockDim.x) {
        const unsigned v = w[i];
        if (v == 0x3F800000u) hasF = 1;
        if (v & 0xFFFFFF00u)  hasHi = 1;
    }
    if (hasF)  atomicOr(&s_hasF, 1);
    if (hasHi) atomicOr(&s_hasHi, 1);
    __syncthreads();
    if (threadIdx.x == 0)
        g_mask_kind = s_hasF ? 2 : (s_hasHi ? 0 : 1);
}

__global__ void cvt_mask_kernel(const void* __restrict__ src,
                                uint8_t* __restrict__ dst, int n)
{
    const int i = blockIdx.x * blockDim.x + threadIdx.x;
    if (i >= n) return;
    const int k = g_mask_kind;
    uint8_t v;
    if (k == 0)      v = (((const uint8_t*)src)[i] != 0);
    else if (k == 1) v = (((const int*)src)[i] != 0);
    else             v = (((const float*)src)[i] != 0.f);
    dst[i] = v;
}

// ============================================================================
// fp32 -> fp16 conversion (vectorized)
// ============================================================================
__global__ void cvt_h_kernel(const float* __restrict__ src,
                             __half* __restrict__ h, int n4)
{
    const int i = blockIdx.x * blockDim.x + threadIdx.x;
    if (i >= n4) return;
    const float4 v = reinterpret_cast<const float4*>(src)[i];
    __half2 h0 = __floats2half2_rn(v.x, v.y);
    __half2 h1 = __floats2half2_rn(v.z, v.w);
    uint32_t* hp = reinterpret_cast<uint32_t*>(h);
    hp[2 * i]     = *reinterpret_cast<uint32_t*>(&h0);
    hp[2 * i + 1] = *reinterpret_cast<uint32_t*>(&h1);
}

// ============================================================================
// common mma / ldmatrix helpers (proven R9/R11/R12)
// ============================================================================
__device__ __forceinline__ void mma_f16(float* d, const uint32_t* a,
                                        const uint32_t* b)
{
    asm volatile(
        "mma.sync.aligned.m16n8k16.row.col.f32.f16.f16.f32 "
        "{%0,%1,%2,%3}, {%4,%5,%6,%7}, {%8,%9}, {%0,%1,%2,%3};"
        : "+f"(d[0]), "+f"(d[1]), "+f"(d[2]), "+f"(d[3])
        : "r"(a[0]), "r"(a[1]), "r"(a[2]), "r"(a[3]), "r"(b[0]), "r"(b[1]));
}

__device__ __forceinline__ void ldm_x4(uint32_t* r, uint32_t addr)
{
    asm volatile("ldmatrix.sync.aligned.m8n8.x4.shared.b16 {%0,%1,%2,%3}, [%4];"
                 : "=r"(r[0]), "=r"(r[1]), "=r"(r[2]), "=r"(r[3]) : "r"(addr));
}

__device__ __forceinline__ uint32_t smem_u32(const void* p) {
    uint32_t a;
    asm("{ .reg .u64 t; cvta.to.shared.u64 t, %1; cvt.u32.u64 %0, t; }"
        : "=r"(a) : "l"(p));
    return a;
}

// 64B-row swizzle (GEMM tiles: 32 fp16/row)
__device__ __forceinline__ uint32_t swz(int r, int q) {
    return (uint32_t)(r * 64 + ((q ^ ((r >> 1) & 3)) << 4));
}
// 256B-row swizzle (attention tiles: 128 fp16/row)
__device__ __forceinline__ uint32_t swA(int r, int q) {
    return (uint32_t)(r * 256 + ((q ^ (r & 7)) << 4));
}

// ============================================================================
// fp16 single-term GEMM: C = A@W^T (both fp16-quantized), fp32 accum.
// Tile 128x128, BK=32, 256 thr = 8 warps (2M x 4N), warp = 64x32.
// Stage = {Ah, Bh} 128x32 fp16 (8KB each) = 16KB; 3-stage cp.async pipeline.
// MODE 0: KV -> g_kh (fp16) / g_vt (fp16, transposed)
// MODE 1: Q  -> g_qh (fp16)     MODE 2: out-proj -> fp32 + bias + post-mask
// ============================================================================
#define STAGE_B 16384
#define GEMM_SMEM (3 * STAGE_B)

template<int KDIM, int MODE>
__global__ __launch_bounds__(256, 2)
void mma_gemm_h(const __half* __restrict__ Ah_g,
                const __half* __restrict__ Bh_g,
                float* __restrict__ Cout,
                const float* __restrict__ bias)
{
    constexpr int S = KDIM / 32;
    extern __shared__ char smem[];
    const uint32_t sb = smem_u32(smem);

    const int t    = threadIdx.x;
    const int lane = t & 31;
    const int wid  = t >> 5;
    const int wm   = wid >> 2;
    const int wn   = wid & 3;
    const int ntile = blockIdx.x;
    const int mtile = blockIdx.y;
    const int rq = lane >> 2;
    const int pq = lane & 3;

    const int g  = lane >> 3;
    const int lr = lane & 7;
    const int arow_l = wm * 64 + ((g & 1) ? 8 : 0) + lr;
    const int aq_l   = g >> 1;
    const int brow_l = wn * 32 + ((g >= 2) ? 8 : 0) + lr;
    const int bq_l   = g & 1;

    // one stage = 1024 x 16B quads (Ah | Bh), 4 per thread
    auto issue = [&](int s, int buf) {
        #pragma unroll
        for (int i = 0; i < 4; i++) {
            const int idx = t + i * 256;
            const int arr = idx >> 9;          // 0=Ah 1=Bh
            const int rem = idx & 511;
            const int r   = rem >> 2;
            const int q   = rem & 3;
            const __half* gp;
            if (arr == 0) {
                const int gm = mtile * 128 + r;
                const int arow = (MODE == 1) ? ((gm >> 5) * NE + (gm & 31)) : gm;
                gp = Ah_g + (size_t)arow * KDIM + s * 32 + q * 8;
            } else {
                gp = Bh_g + (size_t)(ntile * 128 + r) * KDIM + s * 32 + q * 8;
            }
            const uint32_t dst = sb + buf * STAGE_B + arr * 8192 + swz(r, q);
            asm volatile("cp.async.ca.shared.global [%0], [%1], 16;"
                         :: "r"(dst), "l"(gp));
        }
        asm volatile("cp.async.commit_group;" ::: "memory");
    };

    float acc[4][4][4];
    #pragma unroll
    for (int i = 0; i < 4; i++)
        #pragma unroll
        for (int j = 0; j < 4; j++)
            #pragma unroll
            for (int c = 0; c < 4; c++) acc[i][j][c] = 0.f;

    issue(0, 0);
    issue(1, 1);

    for (int s = 0; s < S; s++) {
        asm volatile("cp.async.wait_group 1;" ::: "memory");
        __syncthreads();
        if (s + 2 < S) issue(s + 2, (s + 2) % 3);
        else asm volatile("cp.async.commit_group;" ::: "memory");

        const uint32_t st = sb + (s % 3) * STAGE_B;   // Ah | Bh(+8K)

        #pragma unroll
        for (int kh = 0; kh < 2; kh++) {
            uint32_t bh[4][2];
            #pragma unroll
            for (int nfp = 0; nfp < 2; nfp++) {
                const uint32_t off = swz(brow_l + nfp * 16, 2 * kh + bq_l);
                uint32_t rh[4];
                ldm_x4(rh, st + 8192 + off);
                bh[2 * nfp][0] = rh[0]; bh[2 * nfp][1] = rh[1];
                bh[2 * nfp + 1][0] = rh[2]; bh[2 * nfp + 1][1] = rh[3];
            }
            #pragma unroll
            for (int mf = 0; mf < 4; mf++) {
                const uint32_t off = swz(arow_l + mf * 16, 2 * kh + aq_l);
                uint32_t ah[4];
                ldm_x4(ah, st + off);
                #pragma unroll
                for (int nf = 0; nf < 4; nf++)
                    mma_f16(acc[mf][nf], ah, bh[nf]);
            }
        }
    }
    asm volatile("cp.async.wait_group 0;" ::: "memory");

    // ---- epilogue ----
    #pragma unroll
    for (int mf = 0; mf < 4; mf++) {
        #pragma unroll
        for (int nf = 0; nf < 4; nf++) {
            const int r0 = mtile * 128 + wm * 64 + mf * 16 + rq;
            const int r1 = r0 + 8;
            const int gn = ntile * 128 + wn * 32 + nf * 8 + pq * 2;
            float2 v0 = make_float2(acc[mf][nf][0], acc[mf][nf][1]);
            float2 v1 = make_float2(acc[mf][nf][2], acc[mf][nf][3]);
            if (MODE == 0) {
                if (gn < EMB) {
                    *reinterpret_cast<__half2*>(&g_kh[(size_t)r0 * EMB + gn]) =
                        __floats2half2_rn(v0.x, v0.y);
                    *reinterpret_cast<__half2*>(&g_kh[(size_t)r1 * EMB + gn]) =
                        __floats2half2_rn(v1.x, v1.y);
                } else {
                    const int d  = gn - EMB;
                    const int bb = r0 >> 7;
                    const int e0 = r0 & 127;
                    __half* vt = g_vt + (size_t)bb * EMB * NE;
                    vt[(size_t)d * NE + e0]           = __float2half_rn(v0.x);
                    vt[(size_t)(d + 1) * NE + e0]     = __float2half_rn(v0.y);
                    vt[(size_t)d * NE + e0 + 8]       = __float2half_rn(v1.x);
                    vt[(size_t)(d + 1) * NE + e0 + 8] = __float2half_rn(v1.y);
                }
            } else if (MODE == 1) {
                *reinterpret_cast<__half2*>(&g_qh[(size_t)r0 * EMB + gn]) =
                    __floats2half2_rn(v0.x, v0.y);
                *reinterpret_cast<__half2*>(&g_qh[(size_t)r1 * EMB + gn]) =
                    __floats2half2_rn(v1.x, v1.y);
            } else {
                const float2 bb = *reinterpret_cast<const float2*>(&bias[gn]);
                v0.x += bb.x; v0.y += bb.y;
                v1.x += bb.x; v1.y += bb.y;
                if (g_post[r0]) { v0.x = 0.f; v0.y = 0.f; }
                if (g_post[r1]) { v1.x = 0.f; v1.y = 0.f; }
                *reinterpret_cast<float2*>(&Cout[(size_t)r0 * EMB + gn]) = v0;
                *reinterpret_cast<float2*>(&Cout[(size_t)r1 * EMB + gn]) = v1;
            }
        }
    }
}

// ============================================================================
// Tensorized attention (R12-proven): one CTA per (b, h), 256 thr = 8 warps.
// smem: qs/ps 8KB @0 | ks 32KB @8K | vs 32KB @40K | ls fp32 32x132 @72K
// ============================================================================
#define ATT_Q 0
#define ATT_K 8192
#define ATT_V 40960
#define ATT_L 73728
#define ATTN_SMEM (73728 + 32 * 132 * 4)   // 90624

__global__ __launch_bounds__(256, 2)
void attn_mma_kernel()
{
    const int b = blockIdx.x;
    const int h = blockIdx.y;
    extern __shared__ char sm[];
    const uint32_t sb = smem_u32(sm);

    const int t    = threadIdx.x;
    const int lane = t & 31;
    const int w    = t >> 5;

    #pragma unroll
    for (int i = 0; i < 2; i++) {                 // q: 512 quads
        const int idx = t + i * 256;
        const int r = idx >> 4, q = idx & 15;
        const __half* gp = g_qh + (size_t)(b * NQ + r) * EMB + h * HD + q * 8;
        asm volatile("cp.async.ca.shared.global [%0], [%1], 16;"
                     :: "r"(sb + ATT_Q + swA(r, q)), "l"(gp));
    }
    #pragma unroll
    for (int i = 0; i < 8; i++) {                 // k: 2048 quads
        const int idx = t + i * 256;
        const int r = idx >> 4, q = idx & 15;
        const __half* gp = g_kh + (size_t)(b * NE + r) * EMB + h * HD + q * 8;
        asm volatile("cp.async.ca.shared.global [%0], [%1], 16;"
                     :: "r"(sb + ATT_K + swA(r, q)), "l"(gp));
    }
    #pragma unroll
    for (int i = 0; i < 8; i++) {                 // v^T: 2048 quads
        const int idx = t + i * 256;
        const int r = idx >> 4, q = idx & 15;
        const __half* gp = g_vt + ((size_t)b * EMB + h * HD + r) * NE + q * 8;
        asm volatile("cp.async.ca.shared.global [%0], [%1], 16;"
                     :: "r"(sb + ATT_V + swA(r, q)), "l"(gp));
    }
    asm volatile("cp.async.commit_group;" ::: "memory");
    asm volatile("cp.async.wait_group 0;" ::: "memory");
    __syncthreads();

    const int g  = lane >> 3;
    const int lr = lane & 7;
    const int arow = ((g & 1) ? 8 : 0) + lr;
    const int aq   = g >> 1;
    const int brow = w * 16 + ((g >= 2) ? 8 : 0) + lr;
    const int bq   = g & 1;
    const int rq = lane >> 2;
    const int pq = lane & 3;

    // ---- S = q @ k^T ----
    float acc[2][2][4];
    #pragma unroll
    for (int i = 0; i < 2; i++)
        #pragma unroll
        for (int j = 0; j < 2; j++)
            #pragma unroll
            for (int c = 0; c < 4; c++) acc[i][j][c] = 0.f;

    #pragma unroll
    for (int kf = 0; kf < 8; kf++) {
        uint32_t a0[4], a1[4], bb[4];
        ldm_x4(a0, sb + ATT_Q + swA(arow,      2 * kf + aq));
        ldm_x4(a1, sb + ATT_Q + swA(arow + 16, 2 * kf + aq));
        ldm_x4(bb, sb + ATT_K + swA(brow,      2 * kf + bq));
        mma_f16(acc[0][0], a0, bb);     mma_f16(acc[0][1], a0, bb + 2);
        mma_f16(acc[1][0], a1, bb);     mma_f16(acc[1][1], a1, bb + 2);
    }

    // ---- masked scaled logits -> ls (fp32) ----
    const float inv_scale = 0.08838834764831845f;   // 1/sqrt(128)
    float* ls = reinterpret_cast<float*>(sm + ATT_L);
    const uint8_t* pm = g_pre + (size_t)b * NQ * NE;
    #pragma unroll
    for (int mf = 0; mf < 2; mf++) {
        #pragma unroll
        for (int nf = 0; nf < 2; nf++) {
            const int row0 = mf * 16 + rq;
            const int row1 = row0 + 8;
            const int col  = w * 16 + nf * 8 + pq * 2;
            ls[row0 * 132 + col]     = pm[row0 * NE + col]     ? -1e30f : acc[mf][nf][0] * inv_scale;
            ls[row0 * 132 + col + 1] = pm[row0 * NE + col + 1] ? -1e30f : acc[mf][nf][1] * inv_scale;
            ls[row1 * 132 + col]     = pm[row1 * NE + col]     ? -1e30f : acc[mf][nf][2] * inv_scale;
            ls[row1 * 132 + col + 1] = pm[row1 * NE + col + 1] ? -1e30f : acc[mf][nf][3] * inv_scale;
        }
    }
    __syncthreads();

    // ---- softmax; P -> fp16 into q's smem region ----
    char* psb = sm + ATT_Q;
    #pragma unroll
    for (int rr = 0; rr < 4; rr++) {
        const int r = w * 4 + rr;
        float x0 = ls[r * 132 + lane];
        float x1 = ls[r * 132 + lane + 32];
        float x2 = ls[r * 132 + lane + 64];
        float x3 = ls[r * 132 + lane + 96];
        float mx = fmaxf(fmaxf(x0, x1), fmaxf(x2, x3));
        #pragma unroll
        for (int off = 16; off; off >>= 1)
            mx = fmaxf(mx, __shfl_xor_sync(0xffffffffu, mx, off));
        float e0 = (x0 <= -1e29f) ? 0.f : expf(x0 - mx);
        float e1 = (x1 <= -1e29f) ? 0.f : expf(x1 - mx);
        float e2 = (x2 <= -1e29f) ? 0.f : expf(x2 - mx);
        float e3 = (x3 <= -1e29f) ? 0.f : expf(x3 - mx);
        float s = e0 + e1 + e2 + e3;
        #pragma unroll
        for (int off = 16; off; off >>= 1)
            s += __shfl_xor_sync(0xffffffffu, s, off);
        const float inv = (s > 0.f) ? (1.f / s) : 0.f;
        const int c0 = lane, c1 = lane + 32, c2 = lane + 64, c3 = lane + 96;
        *reinterpret_cast<__half*>(psb + swA(r, c0 >> 3) + (c0 & 7) * 2) = __float2half_rn(e0 * inv);
        *reinterpret_cast<__half*>(psb + swA(r, c1 >> 3) + (c1 & 7) * 2) = __float2half_rn(e1 * inv);
        *reinterpret_cast<__half*>(psb + swA(r, c2 >> 3) + (c2 & 7) * 2) = __float2half_rn(e2 * inv);
        *reinterpret_cast<__half*>(psb + swA(r, c3 >> 3) + (c3 & 7) * 2) = __float2half_rn(e3 * inv);
    }
    __syncthreads();

    // ---- O = P @ V ----
    float o[2][2][4];
    #pragma unroll
    for (int i = 0; i < 2; i++)
        #pragma unroll
        for (int j = 0; j < 2; j++)
            #pragma unroll
            for (int c = 0; c < 4; c++) o[i][j][c] = 0.f;

    #pragma unroll
    for (int kf = 0; kf < 8; kf++) {
        uint32_t a0[4], a1[4], bb[4];
        ldm_x4(a0, sb + ATT_Q + swA(arow,      2 * kf + aq));
        ldm_x4(a1, sb + ATT_Q + swA(arow + 16, 2 * kf + aq));
        ldm_x4(bb, sb + ATT_V + swA(brow,      2 * kf + bq));
        mma_f16(o[0][0], a0, bb);      mma_f16(o[0][1], a0, bb + 2);
        mma_f16(o[1][0], a1, bb);      mma_f16(o[1][1], a1, bb + 2);
    }

    #pragma unroll
    for (int mf = 0; mf < 2; mf++) {
        #pragma unroll
        for (int nf = 0; nf < 2; nf++) {
            const int row0 = mf * 16 + rq;
            const int row1 = row0 + 8;
            const int col  = w * 16 + nf * 8 + pq * 2;
            *reinterpret_cast<__half2*>(
                &g_aoh[(size_t)(b * NQ + row0) * EMB + h * HD + col]) =
                __floats2half2_rn(o[mf][nf][0], o[mf][nf][1]);
            *reinterpret_cast<__half2*>(
                &g_aoh[(size_t)(b * NQ + row1) * EMB + h * HD + col]) =
                __floats2half2_rn(o[mf][nf][2], o[mf][nf][3]);
        }
    }
}

// ============================================================================
extern "C" void kernel_launch(void* const* d_in, const int* in_sizes, int n_in,
                              void* d_out, int out_size)
{
    const float *entities = nullptr, *W_in = nullptr, *W_out = nullptr,
                *b_out = nullptr;
    const void  *pre_mask = nullptr, *post_mask = nullptr;
    for (int i = 0; i < n_in; i++) {
        switch (in_sizes[i]) {
            case BS * NE * IND:   entities  = (const float*)d_in[i]; break;
            case BS * NQ * NE:    pre_mask  = d_in[i];               break;
            case BS * NQ:         post_mask = d_in[i];               break;
            case 3 * EMB * IND:   W_in      = (const float*)d_in[i]; break;
            case EMB * EMB:       W_out     = (const float*)d_in[i]; break;
            case EMB:             b_out     = (const float*)d_in[i]; break;
        }
    }
    float* out = (float*)d_out;

    cudaFuncSetAttribute(attn_mma_kernel,
                         cudaFuncAttributeMaxDynamicSharedMemorySize, ATTN_SMEM);
    cudaFuncSetAttribute(mma_gemm_h<IND, 0>,
                         cudaFuncAttributeMaxDynamicSharedMemorySize, GEMM_SMEM);
    cudaFuncSetAttribute(mma_gemm_h<IND, 1>,
                         cudaFuncAttributeMaxDynamicSharedMemorySize, GEMM_SMEM);
    cudaFuncSetAttribute(mma_gemm_h<EMB, 2>,
                         cudaFuncAttributeMaxDynamicSharedMemorySize, GEMM_SMEM);

    __half *eh, *wih, *woh, *aoh;
    uint8_t *pre_dst, *post_dst;
    cudaGetSymbolAddress((void**)&eh,  g_eh);
    cudaGetSymbolAddress((void**)&wih, g_wih);
    cudaGetSymbolAddress((void**)&woh, g_woh);
    cudaGetSymbolAddress((void**)&aoh, g_aoh);
    cudaGetSymbolAddress((void**)&pre_dst,  g_pre);
    cudaGetSymbolAddress((void**)&post_dst, g_post);

    // 0) normalize masks + convert operands to fp16
    sniff_kernel<<<1, 256>>>(pre_mask);
    cvt_mask_kernel<<<(BS * NQ * NE + 255) / 256, 256>>>(pre_mask, pre_dst,
                                                         BS * NQ * NE);
    cvt_mask_kernel<<<(BS * NQ + 255) / 256, 256>>>(post_mask, post_dst,
                                                    BS * NQ);
    cvt_h_kernel<<<(BS * NE * IND / 4 + 255) / 256, 256>>>(
        entities, eh, BS * NE * IND / 4);
    cvt_h_kernel<<<(3 * EMB * IND / 4 + 255) / 256, 256>>>(
        W_in, wih, 3 * EMB * IND / 4);
    cvt_h_kernel<<<(EMB * EMB / 4 + 255) / 256, 256>>>(
        W_out, woh, EMB * EMB / 4);

    // 1) K,V projection -> g_kh (fp16), g_vt (fp16 transposed)
    mma_gemm_h<IND, 0><<<dim3(8, BS), 256, GEMM_SMEM>>>(
        eh, wih + (size_t)EMB * IND, nullptr, nullptr);

    // 2) Q projection -> g_qh (fp16)
    mma_gemm_h<IND, 1><<<dim3(4, (BS * NQ) / 128), 256, GEMM_SMEM>>>(
        eh, wih, nullptr, nullptr);

    // 3) tensorized masked attention -> g_aoh (fp16)
    attn_mma_kernel<<<dim3(BS, NH), 256, ATTN_SMEM>>>();

    // 4) output projection + bias + post_mask -> d_out
    mma_gemm_h<EMB, 2><<<dim3(4, (BS * NQ) / 128), 256, GEMM_SMEM>>>(
        aoh, woh, out, b_out);
}

// round 15
// speedup vs baseline: 2.9967x; 1.0941x over previous
#include <cuda_runtime.h>
#include <cuda_fp16.h>
#include <stdint.h>
#include <math.h>

// Problem constants
#define BS   4096
#define NE   128
#define NQ   32
#define IND  256
#define EMB  512
#define NH   4
#define HD   128

// -------- scratch (static device globals; no runtime allocation) --------
__device__ uint8_t g_pre [BS * NQ * NE];
__device__ uint8_t g_post[BS * NQ];
__device__ int     g_mask_kind;
// fp16 operands (single-term)
__device__ __half g_eh [BS * NE * IND];
__device__ __half g_wih[3 * EMB * IND];
__device__ __half g_woh[EMB * EMB];
__device__ __half g_qh [BS * NQ * EMB];        // q  [b*NQ+qi][512]
__device__ __half g_kh [BS * NE * EMB];        // k  [b*NE+e][512]
__device__ __half g_vt [BS * EMB * NE];        // vT [b][d(512)][e(128)]
__device__ __half g_aoh[BS * NQ * EMB];        // attn out fp16

// ============================================================================
// Mask dtype sniffer + normalizer (proven)
// ============================================================================
__global__ void sniff_kernel(const void* __restrict__ pre)
{
    __shared__ int s_hasF, s_hasHi;
    if (threadIdx.x == 0) { s_hasF = 0; s_hasHi = 0; }
    __syncthreads();
    const unsigned* w = (const unsigned*)pre;
    int hasF = 0, hasHi = 0;
    for (int i = threadIdx.x; i < 16384; i += blockDim.x) {
        const unsigned v = w[i];
        if (v == 0x3F800000u) hasF = 1;
        if (v & 0xFFFFFF00u)  hasHi = 1;
    }
    if (hasF)  atomicOr(&s_hasF, 1);
    if (hasHi) atomicOr(&s_hasHi, 1);
    __syncthreads();
    if (threadIdx.x == 0)
        g_mask_kind = s_hasF ? 2 : (s_hasHi ? 0 : 1);
}

__global__ void cvt_mask_kernel(const void* __restrict__ src,
                                uint8_t* __restrict__ dst, int n)
{
    const int i = blockIdx.x * blockDim.x + threadIdx.x;
    if (i >= n) return;
    const int k = g_mask_kind;
    uint8_t v;
    if (k == 0)      v = (((const uint8_t*)src)[i] != 0);
    else if (k == 1) v = (((const int*)src)[i] != 0);
    else             v = (((const float*)src)[i] != 0.f);
    dst[i] = v;
}

// ============================================================================
// fp32 -> fp16 conversion (vectorized)
// ============================================================================
__global__ void cvt_h_kernel(const float* __restrict__ src,
                             __half* __restrict__ h, int n4)
{
    const int i = blockIdx.x * blockDim.x + threadIdx.x;
    if (i >= n4) return;
    const float4 v = reinterpret_cast<const float4*>(src)[i];
    __half2 h0 = __floats2half2_rn(v.x, v.y);
    __half2 h1 = __floats2half2_rn(v.z, v.w);
    uint32_t* hp = reinterpret_cast<uint32_t*>(h);
    hp[2 * i]     = *reinterpret_cast<uint32_t*>(&h0);
    hp[2 * i + 1] = *reinterpret_cast<uint32_t*>(&h1);
}

// ============================================================================
// common mma / ldmatrix helpers (proven)
// ============================================================================
__device__ __forceinline__ void mma_f16(float* d, const uint32_t* a,
                                        const uint32_t* b)
{
    asm volatile(
        "mma.sync.aligned.m16n8k16.row.col.f32.f16.f16.f32 "
        "{%0,%1,%2,%3}, {%4,%5,%6,%7}, {%8,%9}, {%0,%1,%2,%3};"
        : "+f"(d[0]), "+f"(d[1]), "+f"(d[2]), "+f"(d[3])
        : "r"(a[0]), "r"(a[1]), "r"(a[2]), "r"(a[3]), "r"(b[0]), "r"(b[1]));
}

__device__ __forceinline__ void ldm_x4(uint32_t* r, uint32_t addr)
{
    asm volatile("ldmatrix.sync.aligned.m8n8.x4.shared.b16 {%0,%1,%2,%3}, [%4];"
                 : "=r"(r[0]), "=r"(r[1]), "=r"(r[2]), "=r"(r[3]) : "r"(addr));
}

__device__ __forceinline__ uint32_t smem_u32(const void* p) {
    uint32_t a;
    asm("{ .reg .u64 t; cvta.to.shared.u64 t, %1; cvt.u32.u64 %0, t; }"
        : "=r"(a) : "l"(p));
    return a;
}

// 64B-row swizzle (GEMM tiles)
__device__ __forceinline__ uint32_t swz(int r, int q) {
    return (uint32_t)(r * 64 + ((q ^ ((r >> 1) & 3)) << 4));
}
// 256B-row swizzle (attention tiles)
__device__ __forceinline__ uint32_t swA(int r, int q) {
    return (uint32_t)(r * 256 + ((q ^ (r & 7)) << 4));
}

// ============================================================================
// fp16 single-term GEMM with smem-staged coalesced epilogue.
// Tile 128x128, BK=32, 256 thr = 8 warps (2M x 4N), warp = 64x32.
// MODE 0: KV. ntile<4 -> g_kh rows; ntile>=4 -> g_vt (transposed in smem,
//         written as coalesced 256B rows; mtile == batch, rows == e).
// MODE 1: Q -> g_qh.   MODE 2: out-proj -> fp32 + bias + post-mask (direct).
// ============================================================================
#define STAGE_B 16384
#define GEMM_SMEM (3 * STAGE_B)
#define EPSTR 136   // staging row stride in halves (272B, 16B-aligned)

template<int KDIM, int MODE>
__global__ __launch_bounds__(256, 2)
void mma_gemm_h(const __half* __restrict__ Ah_g,
                const __half* __restrict__ Bh_g,
                float* __restrict__ Cout,
                const float* __restrict__ bias)
{
    constexpr int S = KDIM / 32;
    extern __shared__ char smem[];
    const uint32_t sb = smem_u32(smem);

    const int t    = threadIdx.x;
    const int lane = t & 31;
    const int wid  = t >> 5;
    const int wm   = wid >> 2;
    const int wn   = wid & 3;
    const int ntile = blockIdx.x;
    const int mtile = blockIdx.y;
    const int rq = lane >> 2;
    const int pq = lane & 3;

    const int g  = lane >> 3;
    const int lr = lane & 7;
    const int arow_l = wm * 64 + ((g & 1) ? 8 : 0) + lr;
    const int aq_l   = g >> 1;
    const int brow_l = wn * 32 + ((g >= 2) ? 8 : 0) + lr;
    const int bq_l   = g & 1;

    auto issue = [&](int s, int buf) {
        #pragma unroll
        for (int i = 0; i < 4; i++) {
            const int idx = t + i * 256;
            const int arr = idx >> 9;          // 0=Ah 1=Bh
            const int rem = idx & 511;
            const int r   = rem >> 2;
            const int q   = rem & 3;
            const __half* gp;
            if (arr == 0) {
                const int gm = mtile * 128 + r;
                const int arow = (MODE == 1) ? ((gm >> 5) * NE + (gm & 31)) : gm;
                gp = Ah_g + (size_t)arow * KDIM + s * 32 + q * 8;
            } else {
                gp = Bh_g + (size_t)(ntile * 128 + r) * KDIM + s * 32 + q * 8;
            }
            const uint32_t dst = sb + buf * STAGE_B + arr * 8192 + swz(r, q);
            asm volatile("cp.async.ca.shared.global [%0], [%1], 16;"
                         :: "r"(dst), "l"(gp));
        }
        asm volatile("cp.async.commit_group;" ::: "memory");
    };

    float acc[4][4][4];
    #pragma unroll
    for (int i = 0; i < 4; i++)
        #pragma unroll
        for (int j = 0; j < 4; j++)
            #pragma unroll
            for (int c = 0; c < 4; c++) acc[i][j][c] = 0.f;

    issue(0, 0);
    issue(1, 1);

    for (int s = 0; s < S; s++) {
        asm volatile("cp.async.wait_group 1;" ::: "memory");
        __syncthreads();
        if (s + 2 < S) issue(s + 2, (s + 2) % 3);
        else asm volatile("cp.async.commit_group;" ::: "memory");

        const uint32_t st = sb + (s % 3) * STAGE_B;   // Ah | Bh(+8K)

        #pragma unroll
        for (int kh = 0; kh < 2; kh++) {
            uint32_t bh[4][2];
            #pragma unroll
            for (int nfp = 0; nfp < 2; nfp++) {
                const uint32_t off = swz(brow_l + nfp * 16, 2 * kh + bq_l);
                uint32_t rh[4];
                ldm_x4(rh, st + 8192 + off);
                bh[2 * nfp][0] = rh[0]; bh[2 * nfp][1] = rh[1];
                bh[2 * nfp + 1][0] = rh[2]; bh[2 * nfp + 1][1] = rh[3];
            }
            #pragma unroll
            for (int mf = 0; mf < 4; mf++) {
                const uint32_t off = swz(arow_l + mf * 16, 2 * kh + aq_l);
                uint32_t ah[4];
                ldm_x4(ah, st + off);
                #pragma unroll
                for (int nf = 0; nf < 4; nf++)
                    mma_f16(acc[mf][nf], ah, bh[nf]);
            }
        }
    }
    asm volatile("cp.async.wait_group 0;" ::: "memory");

    if (MODE == 0 || MODE == 1) {
        // ---- smem-staged epilogue: fragments -> smem tile -> coalesced STG
        __syncthreads();   // mainloop smem reads done; safe to overwrite
        __half* ep = reinterpret_cast<__half*>(smem);
        const bool vmode = (MODE == 0) && (ntile >= 4);
        #pragma unroll
        for (int mf = 0; mf < 4; mf++) {
            #pragma unroll
            for (int nf = 0; nf < 4; nf++) {
                const int e0 = wm * 64 + mf * 16 + rq;
                const int e1 = e0 + 8;
                const int dl = wn * 32 + nf * 8 + pq * 2;
                if (vmode) {
                    // transpose in smem: ep[d][e]
                    ep[dl * EPSTR + e0]       = __float2half_rn(acc[mf][nf][0]);
                    ep[(dl + 1) * EPSTR + e0] = __float2half_rn(acc[mf][nf][1]);
                    ep[dl * EPSTR + e1]       = __float2half_rn(acc[mf][nf][2]);
                    ep[(dl + 1) * EPSTR + e1] = __float2half_rn(acc[mf][nf][3]);
                } else {
                    *reinterpret_cast<__half2*>(&ep[e0 * EPSTR + dl]) =
                        __floats2half2_rn(acc[mf][nf][0], acc[mf][nf][1]);
                    *reinterpret_cast<__half2*>(&ep[e1 * EPSTR + dl]) =
                        __floats2half2_rn(acc[mf][nf][2], acc[mf][nf][3]);
                }
            }
        }
        __syncthreads();
        // 128 rows x 128 halves = 2048 16B-quads, 8 per thread, coalesced
        #pragma unroll
        for (int i = 0; i < 8; i++) {
            const int idx = t + i * 256;
            const int row = idx >> 4;
            const int q   = idx & 15;
            const float4 v4 =
                *reinterpret_cast<const float4*>(&ep[row * EPSTR + q * 8]);
            __half* dst;
            if (MODE == 1)
                dst = &g_qh[(size_t)(mtile * 128 + row) * EMB + ntile * 128 + q * 8];
            else if (!vmode)
                dst = &g_kh[(size_t)(mtile * 128 + row) * EMB + ntile * 128 + q * 8];
            else   // vt[b=mtile][d=(ntile-4)*128+row][e=q*8..]
                dst = &g_vt[((size_t)mtile * EMB + (ntile - 4) * 128 + row) * NE + q * 8];
            *reinterpret_cast<float4*>(dst) = v4;
        }
    } else {
        // ---- MODE 2 epilogue (direct, fp32 + bias + post-mask) ----
        #pragma unroll
        for (int mf = 0; mf < 4; mf++) {
            #pragma unroll
            for (int nf = 0; nf < 4; nf++) {
                const int r0 = mtile * 128 + wm * 64 + mf * 16 + rq;
                const int r1 = r0 + 8;
                const int gn = ntile * 128 + wn * 32 + nf * 8 + pq * 2;
                float2 v0 = make_float2(acc[mf][nf][0], acc[mf][nf][1]);
                float2 v1 = make_float2(acc[mf][nf][2], acc[mf][nf][3]);
                const float2 bb = *reinterpret_cast<const float2*>(&bias[gn]);
                v0.x += bb.x; v0.y += bb.y;
                v1.x += bb.x; v1.y += bb.y;
                if (g_post[r0]) { v0.x = 0.f; v0.y = 0.f; }
                if (g_post[r1]) { v1.x = 0.f; v1.y = 0.f; }
                *reinterpret_cast<float2*>(&Cout[(size_t)r0 * EMB + gn]) = v0;
                *reinterpret_cast<float2*>(&Cout[(size_t)r1 * EMB + gn]) = v1;
            }
        }
    }
}

// ============================================================================
// Tensorized attention (R12-proven): one CTA per (b, h), 256 thr = 8 warps.
// smem: qs/ps 8KB @0 | ks 32KB @8K | vs 32KB @40K | ls fp32 32x132 @72K
// ============================================================================
#define ATT_Q 0
#define ATT_K 8192
#define ATT_V 40960
#define ATT_L 73728
#define ATTN_SMEM (73728 + 32 * 132 * 4)   // 90624

__global__ __launch_bounds__(256, 2)
void attn_mma_kernel()
{
    const int b = blockIdx.x;
    const int h = blockIdx.y;
    extern __shared__ char sm[];
    const uint32_t sb = smem_u32(sm);

    const int t    = threadIdx.x;
    const int lane = t & 31;
    const int w    = t >> 5;

    #pragma unroll
    for (int i = 0; i < 2; i++) {                 // q: 512 quads
        const int idx = t + i * 256;
        const int r = idx >> 4, q = idx & 15;
        const __half* gp = g_qh + (size_t)(b * NQ + r) * EMB + h * HD + q * 8;
        asm volatile("cp.async.ca.shared.global [%0], [%1], 16;"
                     :: "r"(sb + ATT_Q + swA(r, q)), "l"(gp));
    }
    #pragma unroll
    for (int i = 0; i < 8; i++) {                 // k: 2048 quads
        const int idx = t + i * 256;
        const int r = idx >> 4, q = idx & 15;
        const __half* gp = g_kh + (size_t)(b * NE + r) * EMB + h * HD + q * 8;
        asm volatile("cp.async.ca.shared.global [%0], [%1], 16;"
                     :: "r"(sb + ATT_K + swA(r, q)), "l"(gp));
    }
    #pragma unroll
    for (int i = 0; i < 8; i++) {                 // v^T: 2048 quads
        const int idx = t + i * 256;
        const int r = idx >> 4, q = idx & 15;
        const __half* gp = g_vt + ((size_t)b * EMB + h * HD + r) * NE + q * 8;
        asm volatile("cp.async.ca.shared.global [%0], [%1], 16;"
                     :: "r"(sb + ATT_V + swA(r, q)), "l"(gp));
    }
    asm volatile("cp.async.commit_group;" ::: "memory");
    asm volatile("cp.async.wait_group 0;" ::: "memory");
    __syncthreads();

    const int g  = lane >> 3;
    const int lr = lane & 7;
    const int arow = ((g & 1) ? 8 : 0) + lr;
    const int aq   = g >> 1;
    const int brow = w * 16 + ((g >= 2) ? 8 : 0) + lr;
    const int bq   = g & 1;
    const int rq = lane >> 2;
    const int pq = lane & 3;

    // ---- S = q @ k^T ----
    float acc[2][2][4];
    #pragma unroll
    for (int i = 0; i < 2; i++)
        #pragma unroll
        for (int j = 0; j < 2; j++)
            #pragma unroll
            for (int c = 0; c < 4; c++) acc[i][j][c] = 0.f;

    #pragma unroll
    for (int kf = 0; kf < 8; kf++) {
        uint32_t a0[4], a1[4], bb[4];
        ldm_x4(a0, sb + ATT_Q + swA(arow,      2 * kf + aq));
        ldm_x4(a1, sb + ATT_Q + swA(arow + 16, 2 * kf + aq));
        ldm_x4(bb, sb + ATT_K + swA(brow,      2 * kf + bq));
        mma_f16(acc[0][0], a0, bb);     mma_f16(acc[0][1], a0, bb + 2);
        mma_f16(acc[1][0], a1, bb);     mma_f16(acc[1][1], a1, bb + 2);
    }

    // ---- masked scaled logits -> ls (fp32) ----
    const float inv_scale = 0.08838834764831845f;   // 1/sqrt(128)
    float* ls = reinterpret_cast<float*>(sm + ATT_L);
    const uint8_t* pm = g_pre + (size_t)b * NQ * NE;
    #pragma unroll
    for (int mf = 0; mf < 2; mf++) {
        #pragma unroll
        for (int nf = 0; nf < 2; nf++) {
            const int row0 = mf * 16 + rq;
            const int row1 = row0 + 8;
            const int col  = w * 16 + nf * 8 + pq * 2;
            ls[row0 * 132 + col]     = pm[row0 * NE + col]     ? -1e30f : acc[mf][nf][0] * inv_scale;
            ls[row0 * 132 + col + 1] = pm[row0 * NE + col + 1] ? -1e30f : acc[mf][nf][1] * inv_scale;
            ls[row1 * 132 + col]     = pm[row1 * NE + col]     ? -1e30f : acc[mf][nf][2] * inv_scale;
            ls[row1 * 132 + col + 1] = pm[row1 * NE + col + 1] ? -1e30f : acc[mf][nf][3] * inv_scale;
        }
    }
    __syncthreads();

    // ---- softmax; P -> fp16 into q's smem region ----
    char* psb = sm + ATT_Q;
    #pragma unroll
    for (int rr = 0; rr < 4; rr++) {
        const int r = w * 4 + rr;
        float x0 = ls[r * 132 + lane];
        float x1 = ls[r * 132 + lane + 32];
        float x2 = ls[r * 132 + lane + 64];
        float x3 = ls[r * 132 + lane + 96];
        float mx = fmaxf(fmaxf(x0, x1), fmaxf(x2, x3));
        #pragma unroll
        for (int off = 16; off; off >>= 1)
            mx = fmaxf(mx, __shfl_xor_sync(0xffffffffu, mx, off));
        float e0 = (x0 <= -1e29f) ? 0.f : expf(x0 - mx);
        float e1 = (x1 <= -1e29f) ? 0.f : expf(x1 - mx);
        float e2 = (x2 <= -1e29f) ? 0.f : expf(x2 - mx);
        float e3 = (x3 <= -1e29f) ? 0.f : expf(x3 - mx);
        float s = e0 + e1 + e2 + e3;
        #pragma unroll
        for (int off = 16; off; off >>= 1)
            s += __shfl_xor_sync(0xffffffffu, s, off);
        const float inv = (s > 0.f) ? (1.f / s) : 0.f;
        const int c0 = lane, c1 = lane + 32, c2 = lane + 64, c3 = lane + 96;
        *reinterpret_cast<__half*>(psb + swA(r, c0 >> 3) + (c0 & 7) * 2) = __float2half_rn(e0 * inv);
        *reinterpret_cast<__half*>(psb + swA(r, c1 >> 3) + (c1 & 7) * 2) = __float2half_rn(e1 * inv);
        *reinterpret_cast<__half*>(psb + swA(r, c2 >> 3) + (c2 & 7) * 2) = __float2half_rn(e2 * inv);
        *reinterpret_cast<__half*>(psb + swA(r, c3 >> 3) + (c3 & 7) * 2) = __float2half_rn(e3 * inv);
    }
    __syncthreads();

    // ---- O = P @ V ----
    float o[2][2][4];
    #pragma unroll
    for (int i = 0; i < 2; i++)
        #pragma unroll
        for (int j = 0; j < 2; j++)
            #pragma unroll
            for (int c = 0; c < 4; c++) o[i][j][c] = 0.f;

    #pragma unroll
    for (int kf = 0; kf < 8; kf++) {
        uint32_t a0[4], a1[4], bb[4];
        ldm_x4(a0, sb + ATT_Q + swA(arow,      2 * kf + aq));
        ldm_x4(a1, sb + ATT_Q + swA(arow + 16, 2 * kf + aq));
        ldm_x4(bb, sb + ATT_V + swA(brow,      2 * kf + bq));
        mma_f16(o[0][0], a0, bb);      mma_f16(o[0][1], a0, bb + 2);
        mma_f16(o[1][0], a1, bb);      mma_f16(o[1][1], a1, bb + 2);
    }

    #pragma unroll
    for (int mf = 0; mf < 2; mf++) {
        #pragma unroll
        for (int nf = 0; nf < 2; nf++) {
            const int row0 = mf * 16 + rq;
            const int row1 = row0 + 8;
            const int col  = w * 16 + nf * 8 + pq * 2;
            *reinterpret_cast<__half2*>(
                &g_aoh[(size_t)(b * NQ + row0) * EMB + h * HD + col]) =
                __floats2half2_rn(o[mf][nf][0], o[mf][nf][1]);
            *reinterpret_cast<__half2*>(
                &g_aoh[(size_t)(b * NQ + row1) * EMB + h * HD + col]) =
                __floats2half2_rn(o[mf][nf][2], o[mf][nf][3]);
        }
    }
}

// ============================================================================
extern "C" void kernel_launch(void* const* d_in, const int* in_sizes, int n_in,
                              void* d_out, int out_size)
{
    const float *entities = nullptr, *W_in = nullptr, *W_out = nullptr,
                *b_out = nullptr;
    const void  *pre_mask = nullptr, *post_mask = nullptr;
    for (int i = 0; i < n_in; i++) {
        switch (in_sizes[i]) {
            case BS * NE * IND:   entities  = (const float*)d_in[i]; break;
            case BS * NQ * NE:    pre_mask  = d_in[i];               break;
            case BS * NQ:         post_mask = d_in[i];               break;
            case 3 * EMB * IND:   W_in      = (const float*)d_in[i]; break;
            case EMB * EMB:       W_out     = (const float*)d_in[i]; break;
            case EMB:             b_out     = (const float*)d_in[i]; break;
        }
    }
    float* out = (float*)d_out;

    cudaFuncSetAttribute(attn_mma_kernel,
                         cudaFuncAttributeMaxDynamicSharedMemorySize, ATTN_SMEM);
    cudaFuncSetAttribute(mma_gemm_h<IND, 0>,
                         cudaFuncAttributeMaxDynamicSharedMemorySize, GEMM_SMEM);
    cudaFuncSetAttribute(mma_gemm_h<IND, 1>,
                         cudaFuncAttributeMaxDynamicSharedMemorySize, GEMM_SMEM);
    cudaFuncSetAttribute(mma_gemm_h<EMB, 2>,
                         cudaFuncAttributeMaxDynamicSharedMemorySize, GEMM_SMEM);

    __half *eh, *wih, *woh, *aoh;
    uint8_t *pre_dst, *post_dst;
    cudaGetSymbolAddress((void**)&eh,  g_eh);
    cudaGetSymbolAddress((void**)&wih, g_wih);
    cudaGetSymbolAddress((void**)&woh, g_woh);
    cudaGetSymbolAddress((void**)&aoh, g_aoh);
    cudaGetSymbolAddress((void**)&pre_dst,  g_pre);
    cudaGetSymbolAddress((void**)&post_dst, g_post);

    // 0) normalize masks + convert operands to fp16
    sniff_kernel<<<1, 256>>>(pre_mask);
    cvt_mask_kernel<<<(BS * NQ * NE + 255) / 256, 256>>>(pre_mask, pre_dst,
                                                         BS * NQ * NE);
    cvt_mask_kernel<<<(BS * NQ + 255) / 256, 256>>>(post_mask, post_dst,
                                                    BS * NQ);
    cvt_h_kernel<<<(BS * NE * IND / 4 + 255) / 256, 256>>>(
        entities, eh, BS * NE * IND / 4);
    cvt_h_kernel<<<(3 * EMB * IND / 4 + 255) / 256, 256>>>(
        W_in, wih, 3 * EMB * IND / 4);
    cvt_h_kernel<<<(EMB * EMB / 4 + 255) / 256, 256>>>(
        W_out, woh, EMB * EMB / 4);

    // 1) K,V projection -> g_kh (fp16), g_vt (fp16 transposed)
    mma_gemm_h<IND, 0><<<dim3(8, BS), 256, GEMM_SMEM>>>(
        eh, wih + (size_t)EMB * IND, nullptr, nullptr);

    // 2) Q projection -> g_qh (fp16)
    mma_gemm_h<IND, 1><<<dim3(4, (BS * NQ) / 128), 256, GEMM_SMEM>>>(
        eh, wih, nullptr, nullptr);

    // 3) tensorized masked attention -> g_aoh (fp16)
    attn_mma_kernel<<<dim3(BS, NH), 256, ATTN_SMEM>>>();

    // 4) output projection + bias + post_mask -> d_out
    mma_gemm_h<EMB, 2><<<dim3(4, (BS * NQ) / 128), 256, GEMM_SMEM>>>(
        aoh, woh, out, b_out);
}

// round 16
// speedup vs baseline: 3.4480x; 1.1506x over previous
#include <cuda_runtime.h>
#include <cuda_fp16.h>
#include <stdint.h>
#include <math.h>

// Problem constants
#define BS   4096
#define NE   128
#define NQ   32
#define IND  256
#define EMB  512
#define NH   4
#define HD   128

// -------- scratch (static device globals; no runtime allocation) --------
__device__ uint8_t g_pre [BS * NQ * NE];
__device__ uint8_t g_post[BS * NQ];
__device__ int     g_mask_kind;
// fp16 operands (single-term)
__device__ __half g_eh [BS * NE * IND];
__device__ __half g_wih[3 * EMB * IND];
__device__ __half g_woh[EMB * EMB];
__device__ __half g_qh [BS * NQ * EMB];        // q  [b*NQ+qi][512]
__device__ __half g_kh [BS * NE * EMB];        // k  [b*NE+e][512]
__device__ __half g_vt [BS * EMB * NE];        // vT [b][d(512)][e(128)]
__device__ __half g_aoh[BS * NQ * EMB];        // attn out fp16

// ============================================================================
// Mask dtype sniffer + normalizer (proven)
// ============================================================================
__global__ void sniff_kernel(const void* __restrict__ pre)
{
    __shared__ int s_hasF, s_hasHi;
    if (threadIdx.x == 0) { s_hasF = 0; s_hasHi = 0; }
    __syncthreads();
    const unsigned* w = (const unsigned*)pre;
    int hasF = 0, hasHi = 0;
    for (int i = threadIdx.x; i < 16384; i += blockDim.x) {
        const unsigned v = w[i];
        if (v == 0x3F800000u) hasF = 1;
        if (v & 0xFFFFFF00u)  hasHi = 1;
    }
    if (hasF)  atomicOr(&s_hasF, 1);
    if (hasHi) atomicOr(&s_hasHi, 1);
    __syncthreads();
    if (threadIdx.x == 0)
        g_mask_kind = s_hasF ? 2 : (s_hasHi ? 0 : 1);
}

__global__ void cvt_mask_kernel(const void* __restrict__ src,
                                uint8_t* __restrict__ dst, int n)
{
    const int i = blockIdx.x * blockDim.x + threadIdx.x;
    if (i >= n) return;
    const int k = g_mask_kind;
    uint8_t v;
    if (k == 0)      v = (((const uint8_t*)src)[i] != 0);
    else if (k == 1) v = (((const int*)src)[i] != 0);
    else             v = (((const float*)src)[i] != 0.f);
    dst[i] = v;
}

// ============================================================================
// fp32 -> fp16 conversion (vectorized)
// ============================================================================
__global__ void cvt_h_kernel(const float* __restrict__ src,
                             __half* __restrict__ h, int n4)
{
    const int i = blockIdx.x * blockDim.x + threadIdx.x;
    if (i >= n4) return;
    const float4 v = reinterpret_cast<const float4*>(src)[i];
    __half2 h0 = __floats2half2_rn(v.x, v.y);
    __half2 h1 = __floats2half2_rn(v.z, v.w);
    uint32_t* hp = reinterpret_cast<uint32_t*>(h);
    hp[2 * i]     = *reinterpret_cast<uint32_t*>(&h0);
    hp[2 * i + 1] = *reinterpret_cast<uint32_t*>(&h1);
}

// ============================================================================
// common mma / ldmatrix helpers (proven)
// ============================================================================
__device__ __forceinline__ void mma_f16(float* d, const uint32_t* a,
                                        const uint32_t* b)
{
    asm volatile(
        "mma.sync.aligned.m16n8k16.row.col.f32.f16.f16.f32 "
        "{%0,%1,%2,%3}, {%4,%5,%6,%7}, {%8,%9}, {%0,%1,%2,%3};"
        : "+f"(d[0]), "+f"(d[1]), "+f"(d[2]), "+f"(d[3])
        : "r"(a[0]), "r"(a[1]), "r"(a[2]), "r"(a[3]), "r"(b[0]), "r"(b[1]));
}

__device__ __forceinline__ void ldm_x4(uint32_t* r, uint32_t addr)
{
    asm volatile("ldmatrix.sync.aligned.m8n8.x4.shared.b16 {%0,%1,%2,%3}, [%4];"
                 : "=r"(r[0]), "=r"(r[1]), "=r"(r[2]), "=r"(r[3]) : "r"(addr));
}

__device__ __forceinline__ uint32_t smem_u32(const void* p) {
    uint32_t a;
    asm("{ .reg .u64 t; cvta.to.shared.u64 t, %1; cvt.u32.u64 %0, t; }"
        : "=r"(a) : "l"(p));
    return a;
}

// 64B-row swizzle (GEMM tiles)
__device__ __forceinline__ uint32_t swz(int r, int q) {
    return (uint32_t)(r * 64 + ((q ^ ((r >> 1) & 3)) << 4));
}
// 256B-row swizzle (attention tiles)
__device__ __forceinline__ uint32_t swA(int r, int q) {
    return (uint32_t)(r * 256 + ((q ^ (r & 7)) << 4));
}

// ============================================================================
// fp16 single-term GEMM, smem-staged coalesced epilogue (R15-proven core).
// MODE 0: merged QKV, 1-D grid 36864 CTAs:
//   bid < 32768: KV   (ntile = bid&7, mtile = bid>>3; ntile<4 -> kh, else vt)
//   bid >= 32768: Q   (ntile = r&3,  mtile = r>>2; A rows gathered)
// MODE 2: out-proj (2-D grid), fp32 + bias + post-mask, direct epilogue.
// ============================================================================
#define STAGE_B 16384
#define GEMM_SMEM (3 * STAGE_B)
#define EPSTR 136   // staging row stride in halves (272B, 16B-aligned)

template<int KDIM, int MODE>
__global__ __launch_bounds__(256, 2)
void mma_gemm_h(const __half* __restrict__ Ah_g,
                const __half* __restrict__ Bkv_g,   // KV weights (or MODE2 W)
                const __half* __restrict__ Bq_g,    // Q weights (MODE 0 only)
                float* __restrict__ Cout,
                const float* __restrict__ bias)
{
    constexpr int S = KDIM / 32;
    extern __shared__ char smem[];
    const uint32_t sb = smem_u32(smem);

    const int t    = threadIdx.x;
    const int lane = t & 31;
    const int wid  = t >> 5;
    const int wm   = wid >> 2;
    const int wn   = wid & 3;

    int ntile, mtile;
    bool qmode = false;
    if (MODE == 0) {
        const int bid = blockIdx.x;
        if (bid < 32768) { ntile = bid & 7; mtile = bid >> 3; }
        else { const int r = bid - 32768; ntile = r & 3; mtile = r >> 2; qmode = true; }
    } else {
        ntile = blockIdx.x; mtile = blockIdx.y;
    }
    const __half* Bh_g = (MODE == 0 && qmode) ? Bq_g : Bkv_g;

    const int rq = lane >> 2;
    const int pq = lane & 3;
    const int g  = lane >> 3;
    const int lr = lane & 7;
    const int arow_l = wm * 64 + ((g & 1) ? 8 : 0) + lr;
    const int aq_l   = g >> 1;
    const int brow_l = wn * 32 + ((g >= 2) ? 8 : 0) + lr;
    const int bq_l   = g & 1;

    auto issue = [&](int s, int buf) {
        #pragma unroll
        for (int i = 0; i < 4; i++) {
            const int idx = t + i * 256;
            const int arr = idx >> 9;          // 0=Ah 1=Bh
            const int rem = idx & 511;
            const int r   = rem >> 2;
            const int q   = rem & 3;
            const __half* gp;
            if (arr == 0) {
                const int gm = mtile * 128 + r;
                const int arow = (MODE == 0 && qmode)
                                 ? ((gm >> 5) * NE + (gm & 31)) : gm;
                gp = Ah_g + (size_t)arow * KDIM + s * 32 + q * 8;
            } else {
                gp = Bh_g + (size_t)(ntile * 128 + r) * KDIM + s * 32 + q * 8;
            }
            const uint32_t dst = sb + buf * STAGE_B + arr * 8192 + swz(r, q);
            asm volatile("cp.async.cg.shared.global [%0], [%1], 16;"
                         :: "r"(dst), "l"(gp));
        }
        asm volatile("cp.async.commit_group;" ::: "memory");
    };

    float acc[4][4][4];
    #pragma unroll
    for (int i = 0; i < 4; i++)
        #pragma unroll
        for (int j = 0; j < 4; j++)
            #pragma unroll
            for (int c = 0; c < 4; c++) acc[i][j][c] = 0.f;

    issue(0, 0);
    issue(1, 1);

    for (int s = 0; s < S; s++) {
        asm volatile("cp.async.wait_group 1;" ::: "memory");
        __syncthreads();
        if (s + 2 < S) issue(s + 2, (s + 2) % 3);
        else asm volatile("cp.async.commit_group;" ::: "memory");

        const uint32_t st = sb + (s % 3) * STAGE_B;   // Ah | Bh(+8K)

        #pragma unroll
        for (int kh = 0; kh < 2; kh++) {
            uint32_t bh[4][2];
            #pragma unroll
            for (int nfp = 0; nfp < 2; nfp++) {
                const uint32_t off = swz(brow_l + nfp * 16, 2 * kh + bq_l);
                uint32_t rh[4];
                ldm_x4(rh, st + 8192 + off);
                bh[2 * nfp][0] = rh[0]; bh[2 * nfp][1] = rh[1];
                bh[2 * nfp + 1][0] = rh[2]; bh[2 * nfp + 1][1] = rh[3];
            }
            #pragma unroll
            for (int mf = 0; mf < 4; mf++) {
                const uint32_t off = swz(arow_l + mf * 16, 2 * kh + aq_l);
                uint32_t ah[4];
                ldm_x4(ah, st + off);
                #pragma unroll
                for (int nf = 0; nf < 4; nf++)
                    mma_f16(acc[mf][nf], ah, bh[nf]);
            }
        }
    }
    asm volatile("cp.async.wait_group 0;" ::: "memory");

    if (MODE == 0) {
        // ---- smem-staged epilogue: fragments -> smem tile -> coalesced STG
        __syncthreads();
        __half* ep = reinterpret_cast<__half*>(smem);
        const bool vmode = (!qmode) && (ntile >= 4);
        #pragma unroll
        for (int mf = 0; mf < 4; mf++) {
            #pragma unroll
            for (int nf = 0; nf < 4; nf++) {
                const int e0 = wm * 64 + mf * 16 + rq;
                const int e1 = e0 + 8;
                const int dl = wn * 32 + nf * 8 + pq * 2;
                if (vmode) {
                    ep[dl * EPSTR + e0]       = __float2half_rn(acc[mf][nf][0]);
                    ep[(dl + 1) * EPSTR + e0] = __float2half_rn(acc[mf][nf][1]);
                    ep[dl * EPSTR + e1]       = __float2half_rn(acc[mf][nf][2]);
                    ep[(dl + 1) * EPSTR + e1] = __float2half_rn(acc[mf][nf][3]);
                } else {
                    *reinterpret_cast<__half2*>(&ep[e0 * EPSTR + dl]) =
                        __floats2half2_rn(acc[mf][nf][0], acc[mf][nf][1]);
                    *reinterpret_cast<__half2*>(&ep[e1 * EPSTR + dl]) =
                        __floats2half2_rn(acc[mf][nf][2], acc[mf][nf][3]);
                }
            }
        }
        __syncthreads();
        #pragma unroll
        for (int i = 0; i < 8; i++) {
            const int idx = t + i * 256;
            const int row = idx >> 4;
            const int q   = idx & 15;
            const float4 v4 =
                *reinterpret_cast<const float4*>(&ep[row * EPSTR + q * 8]);
            __half* dst;
            if (qmode)
                dst = &g_qh[(size_t)(mtile * 128 + row) * EMB + ntile * 128 + q * 8];
            else if (!vmode)
                dst = &g_kh[(size_t)(mtile * 128 + row) * EMB + ntile * 128 + q * 8];
            else
                dst = &g_vt[((size_t)mtile * EMB + (ntile - 4) * 128 + row) * NE + q * 8];
            *reinterpret_cast<float4*>(dst) = v4;
        }
    } else {
        // ---- MODE 2 epilogue (direct, fp32 + bias + post-mask) ----
        #pragma unroll
        for (int mf = 0; mf < 4; mf++) {
            #pragma unroll
            for (int nf = 0; nf < 4; nf++) {
                const int r0 = mtile * 128 + wm * 64 + mf * 16 + rq;
                const int r1 = r0 + 8;
                const int gn = ntile * 128 + wn * 32 + nf * 8 + pq * 2;
                float2 v0 = make_float2(acc[mf][nf][0], acc[mf][nf][1]);
                float2 v1 = make_float2(acc[mf][nf][2], acc[mf][nf][3]);
                const float2 bb = *reinterpret_cast<const float2*>(&bias[gn]);
                v0.x += bb.x; v0.y += bb.y;
                v1.x += bb.x; v1.y += bb.y;
                if (g_post[r0]) { v0.x = 0.f; v0.y = 0.f; }
                if (g_post[r1]) { v1.x = 0.f; v1.y = 0.f; }
                *reinterpret_cast<float2*>(&Cout[(size_t)r0 * EMB + gn]) = v0;
                *reinterpret_cast<float2*>(&Cout[(size_t)r1 * EMB + gn]) = v1;
            }
        }
    }
}

// ============================================================================
// Tensorized attention (R12-proven math) with split-wait v overlap:
// group A = {q, k} awaited before S; group B = {v} awaited only before P@V.
// smem: qs/ps 8KB @0 | ks 32KB @8K | vs 32KB @40K | ls fp32 32x132 @72K
// ============================================================================
#define ATT_Q 0
#define ATT_K 8192
#define ATT_V 40960
#define ATT_L 73728
#define ATTN_SMEM (73728 + 32 * 132 * 4)   // 90624

__global__ __launch_bounds__(256, 2)
void attn_mma_kernel()
{
    const int b = blockIdx.x;
    const int h = blockIdx.y;
    extern __shared__ char sm[];
    const uint32_t sb = smem_u32(sm);

    const int t    = threadIdx.x;
    const int lane = t & 31;
    const int w    = t >> 5;

    // group A: q + k
    #pragma unroll
    for (int i = 0; i < 2; i++) {                 // q: 512 quads
        const int idx = t + i * 256;
        const int r = idx >> 4, q = idx & 15;
        const __half* gp = g_qh + (size_t)(b * NQ + r) * EMB + h * HD + q * 8;
        asm volatile("cp.async.ca.shared.global [%0], [%1], 16;"
                     :: "r"(sb + ATT_Q + swA(r, q)), "l"(gp));
    }
    #pragma unroll
    for (int i = 0; i < 8; i++) {                 // k: 2048 quads
        const int idx = t + i * 256;
        const int r = idx >> 4, q = idx & 15;
        const __half* gp = g_kh + (size_t)(b * NE + r) * EMB + h * HD + q * 8;
        asm volatile("cp.async.ca.shared.global [%0], [%1], 16;"
                     :: "r"(sb + ATT_K + swA(r, q)), "l"(gp));
    }
    asm volatile("cp.async.commit_group;" ::: "memory");
    // group B: v (awaited only before P@V)
    #pragma unroll
    for (int i = 0; i < 8; i++) {                 // v^T: 2048 quads
        const int idx = t + i * 256;
        const int r = idx >> 4, q = idx & 15;
        const __half* gp = g_vt + ((size_t)b * EMB + h * HD + r) * NE + q * 8;
        asm volatile("cp.async.ca.shared.global [%0], [%1], 16;"
                     :: "r"(sb + ATT_V + swA(r, q)), "l"(gp));
    }
    asm volatile("cp.async.commit_group;" ::: "memory");

    asm volatile("cp.async.wait_group 1;" ::: "memory");   // q,k ready
    __syncthreads();

    const int g  = lane >> 3;
    const int lr = lane & 7;
    const int arow = ((g & 1) ? 8 : 0) + lr;
    const int aq   = g >> 1;
    const int brow = w * 16 + ((g >= 2) ? 8 : 0) + lr;
    const int bq   = g & 1;
    const int rq = lane >> 2;
    const int pq = lane & 3;

    // ---- S = q @ k^T ----
    float acc[2][2][4];
    #pragma unroll
    for (int i = 0; i < 2; i++)
        #pragma unroll
        for (int j = 0; j < 2; j++)
            #pragma unroll
            for (int c = 0; c < 4; c++) acc[i][j][c] = 0.f;

    #pragma unroll
    for (int kf = 0; kf < 8; kf++) {
        uint32_t a0[4], a1[4], bb[4];
        ldm_x4(a0, sb + ATT_Q + swA(arow,      2 * kf + aq));
        ldm_x4(a1, sb + ATT_Q + swA(arow + 16, 2 * kf + aq));
        ldm_x4(bb, sb + ATT_K + swA(brow,      2 * kf + bq));
        mma_f16(acc[0][0], a0, bb);     mma_f16(acc[0][1], a0, bb + 2);
        mma_f16(acc[1][0], a1, bb);     mma_f16(acc[1][1], a1, bb + 2);
    }

    // ---- masked scaled logits -> ls (fp32) ----
    const float inv_scale = 0.08838834764831845f;   // 1/sqrt(128)
    float* ls = reinterpret_cast<float*>(sm + ATT_L);
    const uint8_t* pm = g_pre + (size_t)b * NQ * NE;
    #pragma unroll
    for (int mf = 0; mf < 2; mf++) {
        #pragma unroll
        for (int nf = 0; nf < 2; nf++) {
            const int row0 = mf * 16 + rq;
            const int row1 = row0 + 8;
            const int col  = w * 16 + nf * 8 + pq * 2;
            ls[row0 * 132 + col]     = pm[row0 * NE + col]     ? -1e30f : acc[mf][nf][0] * inv_scale;
            ls[row0 * 132 + col + 1] = pm[row0 * NE + col + 1] ? -1e30f : acc[mf][nf][1] * inv_scale;
            ls[row1 * 132 + col]     = pm[row1 * NE + col]     ? -1e30f : acc[mf][nf][2] * inv_scale;
            ls[row1 * 132 + col + 1] = pm[row1 * NE + col + 1] ? -1e30f : acc[mf][nf][3] * inv_scale;
        }
    }
    __syncthreads();

    // ---- softmax; P -> fp16 into q's smem region (v still loading into ATT_V) ----
    char* psb = sm + ATT_Q;
    #pragma unroll
    for (int rr = 0; rr < 4; rr++) {
        const int r = w * 4 + rr;
        float x0 = ls[r * 132 + lane];
        float x1 = ls[r * 132 + lane + 32];
        float x2 = ls[r * 132 + lane + 64];
        float x3 = ls[r * 132 + lane + 96];
        float mx = fmaxf(fmaxf(x0, x1), fmaxf(x2, x3));
        #pragma unroll
        for (int off = 16; off; off >>= 1)
            mx = fmaxf(mx, __shfl_xor_sync(0xffffffffu, mx, off));
        float e0 = (x0 <= -1e29f) ? 0.f : expf(x0 - mx);
        float e1 = (x1 <= -1e29f) ? 0.f : expf(x1 - mx);
        float e2 = (x2 <= -1e29f) ? 0.f : expf(x2 - mx);
        float e3 = (x3 <= -1e29f) ? 0.f : expf(x3 - mx);
        float s = e0 + e1 + e2 + e3;
        #pragma unroll
        for (int off = 16; off; off >>= 1)
            s += __shfl_xor_sync(0xffffffffu, s, off);
        const float inv = (s > 0.f) ? (1.f / s) : 0.f;
        const int c0 = lane, c1 = lane + 32, c2 = lane + 64, c3 = lane + 96;
        *reinterpret_cast<__half*>(psb + swA(r, c0 >> 3) + (c0 & 7) * 2) = __float2half_rn(e0 * inv);
        *reinterpret_cast<__half*>(psb + swA(r, c1 >> 3) + (c1 & 7) * 2) = __float2half_rn(e1 * inv);
        *reinterpret_cast<__half*>(psb + swA(r, c2 >> 3) + (c2 & 7) * 2) = __float2half_rn(e2 * inv);
        *reinterpret_cast<__half*>(psb + swA(r, c3 >> 3) + (c3 & 7) * 2) = __float2half_rn(e3 * inv);
    }
    asm volatile("cp.async.wait_group 0;" ::: "memory");   // v ready
    __syncthreads();

    // ---- O = P @ V ----
    float o[2][2][4];
    #pragma unroll
    for (int i = 0; i < 2; i++)
        #pragma unroll
        for (int j = 0; j < 2; j++)
            #pragma unroll
            for (int c = 0; c < 4; c++) o[i][j][c] = 0.f;

    #pragma unroll
    for (int kf = 0; kf < 8; kf++) {
        uint32_t a0[4], a1[4], bb[4];
        ldm_x4(a0, sb + ATT_Q + swA(arow,      2 * kf + aq));
        ldm_x4(a1, sb + ATT_Q + swA(arow + 16, 2 * kf + aq));
        ldm_x4(bb, sb + ATT_V + swA(brow,      2 * kf + bq));
        mma_f16(o[0][0], a0, bb);      mma_f16(o[0][1], a0, bb + 2);
        mma_f16(o[1][0], a1, bb);      mma_f16(o[1][1], a1, bb + 2);
    }

    #pragma unroll
    for (int mf = 0; mf < 2; mf++) {
        #pragma unroll
        for (int nf = 0; nf < 2; nf++) {
            const int row0 = mf * 16 + rq;
            const int row1 = row0 + 8;
            const int col  = w * 16 + nf * 8 + pq * 2;
            *reinterpret_cast<__half2*>(
                &g_aoh[(size_t)(b * NQ + row0) * EMB + h * HD + col]) =
                __floats2half2_rn(o[mf][nf][0], o[mf][nf][1]);
            *reinterpret_cast<__half2*>(
                &g_aoh[(size_t)(b * NQ + row1) * EMB + h * HD + col]) =
                __floats2half2_rn(o[mf][nf][2], o[mf][nf][3]);
        }
    }
}

// ============================================================================
extern "C" void kernel_launch(void* const* d_in, const int* in_sizes, int n_in,
                              void* d_out, int out_size)
{
    const float *entities = nullptr, *W_in = nullptr, *W_out = nullptr,
                *b_out = nullptr;
    const void  *pre_mask = nullptr, *post_mask = nullptr;
    for (int i = 0; i < n_in; i++) {
        switch (in_sizes[i]) {
            case BS * NE * IND:   entities  = (const float*)d_in[i]; break;
            case BS * NQ * NE:    pre_mask  = d_in[i];               break;
            case BS * NQ:         post_mask = d_in[i];               break;
            case 3 * EMB * IND:   W_in      = (const float*)d_in[i]; break;
            case EMB * EMB:       W_out     = (const float*)d_in[i]; break;
            case EMB:             b_out     = (const float*)d_in[i]; break;
        }
    }
    float* out = (float*)d_out;

    cudaFuncSetAttribute(attn_mma_kernel,
                         cudaFuncAttributeMaxDynamicSharedMemorySize, ATTN_SMEM);
    cudaFuncSetAttribute(mma_gemm_h<IND, 0>,
                         cudaFuncAttributeMaxDynamicSharedMemorySize, GEMM_SMEM);
    cudaFuncSetAttribute(mma_gemm_h<EMB, 2>,
                         cudaFuncAttributeMaxDynamicSharedMemorySize, GEMM_SMEM);

    __half *eh, *wih, *woh, *aoh;
    uint8_t *pre_dst, *post_dst;
    cudaGetSymbolAddress((void**)&eh,  g_eh);
    cudaGetSymbolAddress((void**)&wih, g_wih);
    cudaGetSymbolAddress((void**)&woh, g_woh);
    cudaGetSymbolAddress((void**)&aoh, g_aoh);
    cudaGetSymbolAddress((void**)&pre_dst,  g_pre);
    cudaGetSymbolAddress((void**)&post_dst, g_post);

    // 0) normalize masks + convert operands to fp16
    sniff_kernel<<<1, 256>>>(pre_mask);
    cvt_mask_kernel<<<(BS * NQ * NE + 255) / 256, 256>>>(pre_mask, pre_dst,
                                                         BS * NQ * NE);
    cvt_mask_kernel<<<(BS * NQ + 255) / 256, 256>>>(post_mask, post_dst,
                                                    BS * NQ);
    cvt_h_kernel<<<(BS * NE * IND / 4 + 255) / 256, 256>>>(
        entities, eh, BS * NE * IND / 4);
    cvt_h_kernel<<<(3 * EMB * IND / 4 + 255) / 256, 256>>>(
        W_in, wih, 3 * EMB * IND / 4);
    cvt_h_kernel<<<(EMB * EMB / 4 + 255) / 256, 256>>>(
        W_out, woh, EMB * EMB / 4);

    // 1+2) merged QKV projection -> g_kh, g_vt, g_qh
    mma_gemm_h<IND, 0><<<36864, 256, GEMM_SMEM>>>(
        eh, wih + (size_t)EMB * IND, wih, nullptr, nullptr);

    // 3) tensorized masked attention -> g_aoh (fp16)
    attn_mma_kernel<<<dim3(BS, NH), 256, ATTN_SMEM>>>();

    // 4) output projection + bias + post_mask -> d_out
    mma_gemm_h<EMB, 2><<<dim3(4, (BS * NQ) / 128), 256, GEMM_SMEM>>>(
        aoh, woh, nullptr, out, b_out);
}